// round 10
// baseline (speedup 1.0000x reference)
#include <cuda_runtime.h>
#include <cuda_bf16.h>
#include <math.h>

// Problem dims
#define T_TOK 2048   // B*S
#define DIM   768
#define NH    12
#define NL    4
#define NE    8
#define FF    3072
#define VOC   32000
#define SEQ   512
#define BAT   4
#define HD    64

// ---------------- static scratch (allocation-free rule) ----------------
__device__ float g_x   [T_TOK * DIM];
__device__ float g_emb [T_TOK * DIM];
__device__ float g_tmp [T_TOK * DIM];
__device__ float g_attn[T_TOK * DIM];
__device__ float g_qkv [T_TOK * 3 * DIM];
__device__ float g_scores[(size_t)BAT * NH * SEQ * SEQ];
__device__ float g_h  [(size_t)NE * T_TOK * FF];
__device__ float g_eo [(size_t)NE * T_TOK * DIM];
__device__ float g_gates[T_TOK * NE];

// ---------------- f32x2 helpers (FFMA2 path, 2x fp32 throughput) -------
__device__ __forceinline__ void fma2(unsigned long long &acc,
                                     unsigned long long a,
                                     unsigned long long b) {
    asm("fma.rn.f32x2 %0, %1, %2, %0;" : "+l"(acc) : "l"(a), "l"(b));
}
__device__ __forceinline__ unsigned long long bcast2(float v) {
    unsigned long long r; unsigned int u = __float_as_uint(v);
    asm("mov.b64 %0, {%1, %1};" : "=l"(r) : "r"(u));
    return r;
}
__device__ __forceinline__ float2 unpack2(unsigned long long v) {
    unsigned int lo, hi;
    asm("mov.b64 {%0, %1}, %2;" : "=r"(lo), "=r"(hi) : "l"(v));
    return make_float2(__uint_as_float(lo), __uint_as_float(hi));
}

// ---------------- generic GEMM: C[m,n] = f(alpha*sum_k A[m,k]*B[n,k] + beta*bias[n])
//                                  + c1*add1[m,n] + c2*add2[m,n]
// If qsp != null: c1 = 1-*qsp, c2 = *qsp  (quantum mix, read on device)
// f = exact GELU if do_gelu. Batched via blockIdx.z with element strides.
// Requires M%128==0, N%128==0, K%8==0 (true for every call here).
__global__ __launch_bounds__(256, 2)
void gemm128(const float* __restrict__ A, const float* __restrict__ B,
             const float* __restrict__ bias,
             const float* __restrict__ add1, const float* __restrict__ add2,
             const float* __restrict__ qsp,
             float* __restrict__ C,
             int M, int N, int K,
             long sA, long sB, long sBias, long sC,
             float alpha, float beta, float c1, float c2, int do_gelu)
{
    __shared__ __align__(16) float As[8][128];
    __shared__ __align__(16) float Bs[8][128];

    int bz = blockIdx.z;
    A += (long)bz * sA;
    B += (long)bz * sB;
    C += (long)bz * sC;
    if (bias) bias += (long)bz * sBias;

    const int n0 = blockIdx.x * 128;
    const int m0 = blockIdx.y * 128;

    const int tid = threadIdx.x;
    const int tx = tid & 15, ty = tid >> 4;

    const int lrow = tid >> 1;          // 0..127
    const int lk4  = (tid & 1) * 4;     // 0 or 4
    const float* Ag = A + (long)(m0 + lrow) * K + lk4;
    const float* Bg = B + (long)(n0 + lrow) * K + lk4;

    unsigned long long acc[8][4];
#pragma unroll
    for (int i = 0; i < 8; i++)
#pragma unroll
        for (int j = 0; j < 4; j++) acc[i][j] = 0ULL;

    for (int k0 = 0; k0 < K; k0 += 8) {
        float4 av = *(const float4*)(Ag + k0);
        float4 bv = *(const float4*)(Bg + k0);
        __syncthreads();
        As[lk4+0][lrow] = av.x; As[lk4+1][lrow] = av.y;
        As[lk4+2][lrow] = av.z; As[lk4+3][lrow] = av.w;
        Bs[lk4+0][lrow] = bv.x; Bs[lk4+1][lrow] = bv.y;
        Bs[lk4+2][lrow] = bv.z; Bs[lk4+3][lrow] = bv.w;
        __syncthreads();
#pragma unroll
        for (int kk = 0; kk < 8; kk++) {
            float4 a0 = *(const float4*)&As[kk][ty * 4];
            float4 a1 = *(const float4*)&As[kk][64 + ty * 4];
            ulonglong2 b01 = *(const ulonglong2*)&Bs[kk][tx * 4];
            ulonglong2 b23 = *(const ulonglong2*)&Bs[kk][64 + tx * 4];
            unsigned long long bb[4] = { b01.x, b01.y, b23.x, b23.y };
            float aa[8] = { a0.x, a0.y, a0.z, a0.w, a1.x, a1.y, a1.z, a1.w };
#pragma unroll
            for (int i = 0; i < 8; i++) {
                unsigned long long a2 = bcast2(aa[i]);
#pragma unroll
                for (int j = 0; j < 4; j++) fma2(acc[i][j], a2, bb[j]);
            }
        }
    }

    float cc1 = c1, cc2 = c2;
    if (qsp) { float q = *qsp; cc1 = 1.0f - q; cc2 = q; }

#pragma unroll
    for (int i = 0; i < 8; i++) {
        int row = m0 + ((i < 4) ? (ty * 4 + i) : (64 + ty * 4 + (i - 4)));
#pragma unroll
        for (int j = 0; j < 4; j++) {
            int col = n0 + ((j < 2) ? (tx * 4 + j * 2) : (64 + tx * 4 + (j - 2) * 2));
            float2 p = unpack2(acc[i][j]);
            float v0 = alpha * p.x, v1 = alpha * p.y;
            if (bias) { v0 += beta * bias[col]; v1 += beta * bias[col + 1]; }
            if (do_gelu) {
                v0 = 0.5f * v0 * (1.0f + erff(v0 * 0.7071067811865475f));
                v1 = 0.5f * v1 * (1.0f + erff(v1 * 0.7071067811865475f));
            }
            long idx = (long)row * N + col;
            if (add1) { v0 += cc1 * add1[idx]; v1 += cc1 * add1[idx + 1]; }
            if (add2) { v0 += cc2 * add2[idx]; v1 += cc2 * add2[idx + 1]; }
            C[idx] = v0; C[idx + 1] = v1;
        }
    }
}

// ---------------- embedding gather ----------------
__global__ __launch_bounds__(256)
void embed_kernel(const int* __restrict__ src, const float* __restrict__ W,
                  float* __restrict__ emb)
{
    int t = blockIdx.x, tid = threadIdx.x;
    long row = (long)src[t] * DIM;
#pragma unroll
    for (int k = 0; k < 3; k++)
        emb[(long)t * DIM + tid + k * 256] = W[row + tid + k * 256];
}

// ---------------- attention: scores = scale * Q K^T (per head, 64x64 tiles) ----
__global__ __launch_bounds__(256)
void attn_scores(const float* __restrict__ qkv, float* __restrict__ scores)
{
    __shared__ __align__(16) float Qs[64][64];   // [hd][i]
    __shared__ __align__(16) float Ks[64][64];   // [hd][j]
    int bh = blockIdx.z;
    int b = bh / NH, h = bh % NH;
    int i0 = blockIdx.y * 64;
    int j0 = blockIdx.x * 64;
    int tid = threadIdx.x;
    int tx = tid & 15, ty = tid >> 4;

#pragma unroll
    for (int rep = 0; rep < 4; rep++) {
        int r  = rep * 16 + (tid >> 4);
        int c4 = (tid & 15) * 4;
        float4 q = *(const float4*)&qkv[((long)(b * SEQ + i0 + r)) * (3 * DIM) + h * HD + c4];
        float4 k = *(const float4*)&qkv[((long)(b * SEQ + j0 + r)) * (3 * DIM) + DIM + h * HD + c4];
        Qs[c4+0][r] = q.x; Qs[c4+1][r] = q.y; Qs[c4+2][r] = q.z; Qs[c4+3][r] = q.w;
        Ks[c4+0][r] = k.x; Ks[c4+1][r] = k.y; Ks[c4+2][r] = k.z; Ks[c4+3][r] = k.w;
    }
    __syncthreads();

    float acc[4][4] = {};
#pragma unroll 8
    for (int kk = 0; kk < 64; kk++) {
        float4 qa = *(const float4*)&Qs[kk][ty * 4];
        float4 kb = *(const float4*)&Ks[kk][tx * 4];
        float qr[4] = { qa.x, qa.y, qa.z, qa.w };
        float kr[4] = { kb.x, kb.y, kb.z, kb.w };
#pragma unroll
        for (int i = 0; i < 4; i++)
#pragma unroll
            for (int j = 0; j < 4; j++) acc[i][j] = fmaf(qr[i], kr[j], acc[i][j]);
    }
    const float scale = 0.125f;  // 1/sqrt(64)
    long base = (long)bh * SEQ * SEQ;
#pragma unroll
    for (int i = 0; i < 4; i++)
#pragma unroll
        for (int j = 0; j < 4; j++)
            scores[base + (long)(i0 + ty * 4 + i) * SEQ + j0 + tx * 4 + j] = acc[i][j] * scale;
}

// ---------------- row softmax over 512 ----------------
__global__ __launch_bounds__(256)
void softmax512(float* __restrict__ s)
{
    long base = (long)blockIdx.x * SEQ;
    int tid = threadIdx.x;
    float v0 = s[base + tid], v1 = s[base + 256 + tid];
    __shared__ float red[256];
    red[tid] = fmaxf(v0, v1);
    __syncthreads();
    for (int o = 128; o > 0; o >>= 1) { if (tid < o) red[tid] = fmaxf(red[tid], red[tid + o]); __syncthreads(); }
    float m = red[0];
    __syncthreads();
    float e0 = expf(v0 - m), e1 = expf(v1 - m);
    red[tid] = e0 + e1;
    __syncthreads();
    for (int o = 128; o > 0; o >>= 1) { if (tid < o) red[tid] += red[tid + o]; __syncthreads(); }
    float inv = 1.0f / red[0];
    s[base + tid] = e0 * inv;
    s[base + 256 + tid] = e1 * inv;
}

// ---------------- attention: O = P V (per head) ----------------
__global__ __launch_bounds__(256)
void attn_av(const float* __restrict__ qkv, const float* __restrict__ scores,
             float* __restrict__ attn)
{
    __shared__ __align__(16) float Ps[32][64];   // [j][i]
    __shared__ __align__(16) float Vs[32][64];   // [j][d]
    int bh = blockIdx.z;
    int b = bh / NH, h = bh % NH;
    int i0 = blockIdx.x * 64;
    int tid = threadIdx.x;
    int tx = tid & 15, ty = tid >> 4;
    long sbase = (long)bh * SEQ * SEQ;

    float acc[4][4] = {};
    for (int j0 = 0; j0 < SEQ; j0 += 32) {
        __syncthreads();
#pragma unroll
        for (int rep = 0; rep < 2; rep++) {
            int idx = rep * 256 + tid;
            int r  = idx >> 3;          // i  0..63
            int c4 = (idx & 7) * 4;     // j  0..28
            float4 p = *(const float4*)&scores[sbase + (long)(i0 + r) * SEQ + j0 + c4];
            Ps[c4+0][r] = p.x; Ps[c4+1][r] = p.y; Ps[c4+2][r] = p.z; Ps[c4+3][r] = p.w;
        }
#pragma unroll
        for (int rep = 0; rep < 2; rep++) {
            int idx = rep * 256 + tid;
            int r  = idx >> 4;          // j  0..31
            int c4 = (idx & 15) * 4;    // d
            float4 v = *(const float4*)&qkv[((long)(b * SEQ + j0 + r)) * (3 * DIM) + 2 * DIM + h * HD + c4];
            *(float4*)&Vs[r][c4] = v;
        }
        __syncthreads();
#pragma unroll
        for (int kk = 0; kk < 32; kk++) {
            float4 pa = *(const float4*)&Ps[kk][ty * 4];
            float4 vb = *(const float4*)&Vs[kk][tx * 4];
            float pr[4] = { pa.x, pa.y, pa.z, pa.w };
            float vr[4] = { vb.x, vb.y, vb.z, vb.w };
#pragma unroll
            for (int i = 0; i < 4; i++)
#pragma unroll
                for (int j = 0; j < 4; j++) acc[i][j] = fmaf(pr[i], vr[j], acc[i][j]);
        }
    }
#pragma unroll
    for (int i = 0; i < 4; i++)
#pragma unroll
        for (int j = 0; j < 4; j++)
            attn[((long)(b * SEQ + i0 + ty * 4 + i)) * DIM + h * HD + tx * 4 + j] = acc[i][j];
}

// ---------------- gating: softmax(gate)*(1+0.1*sigmoid(qgate)), renormalized ---
__global__ __launch_bounds__(256)
void gates_kernel(const float* __restrict__ x, const float* __restrict__ gw,
                  const float* __restrict__ gb, const float* __restrict__ qw,
                  const float* __restrict__ qb, float* __restrict__ gates)
{
    int t = blockIdx.x, tid = threadIdx.x;
    __shared__ float xs[DIM];
    __shared__ float lg[NE], lq[NE];
#pragma unroll
    for (int k = 0; k < 3; k++) xs[tid + k * 256] = x[(long)t * DIM + tid + k * 256];
    __syncthreads();
    int w = tid >> 5, lane = tid & 31;   // 8 warps, warp w -> expert w
    float ag = 0.f, aq = 0.f;
    for (int d = lane; d < DIM; d += 32) {
        float xv = xs[d];
        ag = fmaf(xv, gw[w * DIM + d], ag);
        aq = fmaf(xv, qw[w * DIM + d], aq);
    }
    for (int o = 16; o > 0; o >>= 1) {
        ag += __shfl_down_sync(0xffffffffu, ag, o);
        aq += __shfl_down_sync(0xffffffffu, aq, o);
    }
    if (lane == 0) { lg[w] = ag + gb[w]; lq[w] = aq + qb[w]; }
    __syncthreads();
    if (tid == 0) {
        float m = lg[0];
        for (int e = 1; e < NE; e++) m = fmaxf(m, lg[e]);
        float ex[NE], s = 0.f;
        for (int e = 0; e < NE; e++) { ex[e] = expf(lg[e] - m); s += ex[e]; }
        float gg[NE], tot = 0.f;
        for (int e = 0; e < NE; e++) {
            float sm = ex[e] / s;
            float sg = 1.0f / (1.0f + expf(-lq[e]));
            gg[e] = sm * (1.0f + 0.1f * sg);
            tot += gg[e];
        }
        for (int e = 0; e < NE; e++) gates[t * NE + e] = gg[e] / tot;
    }
}

// ---------------- MoE combine + residual + LayerNorm (in-place on x) ----------
__global__ __launch_bounds__(256)
void moe_ln(const float* __restrict__ eo, const float* __restrict__ gates,
            float* __restrict__ x, const float* __restrict__ lng,
            const float* __restrict__ lnb)
{
    int t = blockIdx.x, tid = threadIdx.x;
    __shared__ float gs[NE];
    __shared__ float red[256];
    if (tid < NE) gs[tid] = gates[t * NE + tid];
    __syncthreads();
    float y[3];
    float s = 0.f;
#pragma unroll
    for (int k = 0; k < 3; k++) {
        int d = tid + k * 256;
        float m = 0.f;
#pragma unroll
        for (int e = 0; e < NE; e++)
            m = fmaf(gs[e], eo[((long)e * T_TOK + t) * DIM + d], m);
        float v = x[(long)t * DIM + d] + m;
        y[k] = v; s += v;
    }
    red[tid] = s; __syncthreads();
    for (int o = 128; o > 0; o >>= 1) { if (tid < o) red[tid] += red[tid + o]; __syncthreads(); }
    float mean = red[0] * (1.0f / DIM);
    __syncthreads();
    float s2 = 0.f;
#pragma unroll
    for (int k = 0; k < 3; k++) { float d0 = y[k] - mean; s2 += d0 * d0; }
    red[tid] = s2; __syncthreads();
    for (int o = 128; o > 0; o >>= 1) { if (tid < o) red[tid] += red[tid + o]; __syncthreads(); }
    float inv = rsqrtf(red[0] * (1.0f / DIM) + 1e-5f);
#pragma unroll
    for (int k = 0; k < 3; k++) {
        int d = tid + k * 256;
        x[(long)t * DIM + d] = (y[k] - mean) * inv * lng[d] + lnb[d];
    }
}

// ---------------- host driver ----------------
static void launch_gemm(const float* A, const float* B, const float* bias,
                        const float* add1, const float* add2, const float* qs,
                        float* C, int M, int N, int K,
                        long sA, long sB, long sBias, long sC, int batch,
                        float alpha, float beta, float c1, float c2, int gelu)
{
    dim3 grid(N / 128, M / 128, batch);
    gemm128<<<grid, 256>>>(A, B, bias, add1, add2, qs, C, M, N, K,
                           sA, sB, sBias, sC, alpha, beta, c1, c2, gelu);
}

extern "C" void kernel_launch(void* const* d_in, const int* in_sizes, int n_in,
                              void* d_out, int out_size)
{
    const int*   src       = (const int*)  d_in[0];
    const float* qs        = (const float*)d_in[1];   // quantum_state [1] (device)
    const float* noise     = (const float*)d_in[2];
    const float* embed_W   = (const float*)d_in[3];
    const float* qproj_w   = (const float*)d_in[4];
    const float* qproj_b   = (const float*)d_in[5];
    const float* pos_w     = (const float*)d_in[6];
    const float* pos_b     = (const float*)d_in[7];
    const float* in_proj_w = (const float*)d_in[8];
    const float* in_proj_b = (const float*)d_in[9];
    const float* out_proj_w= (const float*)d_in[10];
    const float* out_proj_b= (const float*)d_in[11];
    const float* ent_w     = (const float*)d_in[12];
    const float* ent_b     = (const float*)d_in[13];
    const float* gate_w    = (const float*)d_in[14];
    const float* gate_b    = (const float*)d_in[15];
    const float* qgate_w   = (const float*)d_in[16];
    const float* qgate_b   = (const float*)d_in[17];
    const float* e_w1      = (const float*)d_in[18];
    const float* e_b1      = (const float*)d_in[19];
    const float* e_w2      = (const float*)d_in[20];
    const float* e_b2      = (const float*)d_in[21];
    const float* ln_g      = (const float*)d_in[22];
    const float* ln_b      = (const float*)d_in[23];
    const float* fc_w      = (const float*)d_in[24];
    const float* fc_b      = (const float*)d_in[25];
    float* out = (float*)d_out;

    float *x, *emb, *tmp, *attn, *qkv, *scores, *hbuf, *eo, *gates;
    cudaGetSymbolAddress((void**)&x,      g_x);
    cudaGetSymbolAddress((void**)&emb,    g_emb);
    cudaGetSymbolAddress((void**)&tmp,    g_tmp);
    cudaGetSymbolAddress((void**)&attn,   g_attn);
    cudaGetSymbolAddress((void**)&qkv,    g_qkv);
    cudaGetSymbolAddress((void**)&scores, g_scores);
    cudaGetSymbolAddress((void**)&hbuf,   g_h);
    cudaGetSymbolAddress((void**)&eo,     g_eo);
    cudaGetSymbolAddress((void**)&gates,  g_gates);

    // --- prologue: quantum embedding + positional mix ---
    embed_kernel<<<T_TOK, 256>>>(src, embed_W, emb);
    // tmp = emb @ qproj^T + qproj_b
    launch_gemm(emb, qproj_w, qproj_b, nullptr, nullptr, nullptr, tmp,
                T_TOK, DIM, DIM, 0, 0, 0, 0, 1, 1.f, 1.f, 0.f, 0.f, 0);
    // x = 0.01*(noise @ pos^T) + pos_b + (1-qs)*emb + qs*tmp
    launch_gemm(noise, pos_w, pos_b, emb, tmp, qs, x,
                T_TOK, DIM, DIM, 0, 0, 0, 0, 1, 0.01f, 1.f, 0.f, 0.f, 0);

    for (int l = 0; l < NL; l++) {
        // qkv = x @ in_proj^T + b
        launch_gemm(x, in_proj_w + (long)l * 3 * DIM * DIM, in_proj_b + l * 3 * DIM,
                    nullptr, nullptr, nullptr, qkv,
                    T_TOK, 3 * DIM, DIM, 0, 0, 0, 0, 1, 1.f, 1.f, 0.f, 0.f, 0);
        attn_scores<<<dim3(SEQ / 64, SEQ / 64, BAT * NH), 256>>>(qkv, scores);
        softmax512<<<BAT * NH * SEQ, 256>>>(scores);
        attn_av<<<dim3(SEQ / 64, 1, BAT * NH), 256>>>(qkv, scores, attn);
        // tmp = attn @ out_proj^T + b
        launch_gemm(attn, out_proj_w + (long)l * DIM * DIM, out_proj_b + l * DIM,
                    nullptr, nullptr, nullptr, tmp,
                    T_TOK, DIM, DIM, 0, 0, 0, 0, 1, 1.f, 1.f, 0.f, 0.f, 0);
        // x = x + tmp + 0.1*(tmp @ ent^T + ent_b)
        launch_gemm(tmp, ent_w + (long)l * DIM * DIM, ent_b + l * DIM,
                    x, tmp, nullptr, x,
                    T_TOK, DIM, DIM, 0, 0, 0, 0, 1, 0.1f, 0.1f, 1.f, 1.f, 0);
        // gates
        gates_kernel<<<T_TOK, 256>>>(x, gate_w + (long)l * NE * DIM, gate_b + l * NE,
                                     qgate_w + (long)l * NE * DIM, qgate_b + l * NE, gates);
        // h[e] = gelu(x @ e_w1[l,e]^T + e_b1[l,e])   (batched over experts)
        launch_gemm(x, e_w1 + (long)l * NE * FF * DIM, e_b1 + (long)l * NE * FF,
                    nullptr, nullptr, nullptr, hbuf,
                    T_TOK, FF, DIM, 0, (long)FF * DIM, FF, (long)T_TOK * FF, NE,
                    1.f, 1.f, 0.f, 0.f, 1);
        // eo[e] = h[e] @ e_w2[l,e]^T + e_b2[l,e]
        launch_gemm(hbuf, e_w2 + (long)l * NE * DIM * FF, e_b2 + (long)l * NE * DIM,
                    nullptr, nullptr, nullptr, eo,
                    T_TOK, DIM, FF, (long)T_TOK * FF, (long)DIM * FF, DIM, (long)T_TOK * DIM, NE,
                    1.f, 1.f, 0.f, 0.f, 0);
        // x = LN(x + sum_e gates[t,e]*eo[e,t,:])
        moe_ln<<<T_TOK, 256>>>(eo, gates, x, ln_g + l * DIM, ln_b + l * DIM);
    }

    // logits = x @ fc_w^T + fc_b
    launch_gemm(x, fc_w, fc_b, nullptr, nullptr, nullptr, out,
                T_TOK, VOC, DIM, 0, 0, 0, 0, 1, 1.f, 1.f, 0.f, 0.f, 0);
}

// round 11
// speedup vs baseline: 1.0533x; 1.0533x over previous
#include <cuda_runtime.h>
#include <cuda_bf16.h>
#include <math.h>

// Problem dims
#define T_TOK 2048   // B*S
#define DIM   768
#define NH    12
#define NL    4
#define NE    8
#define FF    3072
#define VOC   32000
#define SEQ   512
#define BAT   4
#define HD    64

// ---------------- static scratch (allocation-free rule) ----------------
__device__ float g_x   [T_TOK * DIM];
__device__ float g_emb [T_TOK * DIM];
__device__ float g_tmp [T_TOK * DIM];
__device__ float g_attn[T_TOK * DIM];
__device__ float g_qkv [T_TOK * 3 * DIM];
__device__ float g_scores[(size_t)BAT * NH * SEQ * SEQ];
__device__ float g_h  [(size_t)NE * T_TOK * FF];
__device__ float g_eo [(size_t)NE * T_TOK * DIM];
__device__ float g_gates[T_TOK * NE];

// ---------------- f32x2 helpers (FFMA2 path, 2x fp32 throughput) -------
__device__ __forceinline__ void fma2(unsigned long long &acc,
                                     unsigned long long a,
                                     unsigned long long b) {
    asm("fma.rn.f32x2 %0, %1, %2, %0;" : "+l"(acc) : "l"(a), "l"(b));
}
__device__ __forceinline__ unsigned long long bcast2(float v) {
    unsigned long long r; unsigned int u = __float_as_uint(v);
    asm("mov.b64 %0, {%1, %1};" : "=l"(r) : "r"(u));
    return r;
}
__device__ __forceinline__ float2 unpack2(unsigned long long v) {
    unsigned int lo, hi;
    asm("mov.b64 {%0, %1}, %2;" : "=r"(lo), "=r"(hi) : "l"(v));
    return make_float2(__uint_as_float(lo), __uint_as_float(hi));
}

// ---------------- generic GEMM: C[m,n] = f(alpha*sum_k A[m,k]*B[n,k] + beta*bias[n])
//                                  + c1*add1[m,n] + c2*add2[m,n]
// If qsp != null: c1 = 1-*qsp, c2 = *qsp  (quantum mix, read on device)
// f = exact GELU if do_gelu. Batched via blockIdx.z with element strides.
// Requires M%128==0, N%128==0, K%8==0 (true for every call here).
__global__ __launch_bounds__(256, 2)
void gemm128(const float* __restrict__ A, const float* __restrict__ B,
             const float* __restrict__ bias,
             const float* __restrict__ add1, const float* __restrict__ add2,
             const float* __restrict__ qsp,
             float* __restrict__ C,
             int M, int N, int K,
             long sA, long sB, long sBias, long sC,
             float alpha, float beta, float c1, float c2, int do_gelu)
{
    __shared__ __align__(16) float As[8][128];
    __shared__ __align__(16) float Bs[8][128];

    int bz = blockIdx.z;
    A += (long)bz * sA;
    B += (long)bz * sB;
    C += (long)bz * sC;
    if (bias) bias += (long)bz * sBias;

    const int n0 = blockIdx.x * 128;
    const int m0 = blockIdx.y * 128;

    const int tid = threadIdx.x;
    const int tx = tid & 15, ty = tid >> 4;

    const int lrow = tid >> 1;          // 0..127
    const int lk4  = (tid & 1) * 4;     // 0 or 4
    const float* Ag = A + (long)(m0 + lrow) * K + lk4;
    const float* Bg = B + (long)(n0 + lrow) * K + lk4;

    unsigned long long acc[8][4];
#pragma unroll
    for (int i = 0; i < 8; i++)
#pragma unroll
        for (int j = 0; j < 4; j++) acc[i][j] = 0ULL;

    for (int k0 = 0; k0 < K; k0 += 8) {
        float4 av = *(const float4*)(Ag + k0);
        float4 bv = *(const float4*)(Bg + k0);
        __syncthreads();
        As[lk4+0][lrow] = av.x; As[lk4+1][lrow] = av.y;
        As[lk4+2][lrow] = av.z; As[lk4+3][lrow] = av.w;
        Bs[lk4+0][lrow] = bv.x; Bs[lk4+1][lrow] = bv.y;
        Bs[lk4+2][lrow] = bv.z; Bs[lk4+3][lrow] = bv.w;
        __syncthreads();
#pragma unroll
        for (int kk = 0; kk < 8; kk++) {
            float4 a0 = *(const float4*)&As[kk][ty * 4];
            float4 a1 = *(const float4*)&As[kk][64 + ty * 4];
            ulonglong2 b01 = *(const ulonglong2*)&Bs[kk][tx * 4];
            ulonglong2 b23 = *(const ulonglong2*)&Bs[kk][64 + tx * 4];
            unsigned long long bb[4] = { b01.x, b01.y, b23.x, b23.y };
            float aa[8] = { a0.x, a0.y, a0.z, a0.w, a1.x, a1.y, a1.z, a1.w };
#pragma unroll
            for (int i = 0; i < 8; i++) {
                unsigned long long a2 = bcast2(aa[i]);
#pragma unroll
                for (int j = 0; j < 4; j++) fma2(acc[i][j], a2, bb[j]);
            }
        }
    }

    float cc1 = c1, cc2 = c2;
    if (qsp) { float q = *qsp; cc1 = 1.0f - q; cc2 = q; }

#pragma unroll
    for (int i = 0; i < 8; i++) {
        int row = m0 + ((i < 4) ? (ty * 4 + i) : (64 + ty * 4 + (i - 4)));
#pragma unroll
        for (int j = 0; j < 4; j++) {
            int col = n0 + ((j < 2) ? (tx * 4 + j * 2) : (64 + tx * 4 + (j - 2) * 2));
            float2 p = unpack2(acc[i][j]);
            float v0 = alpha * p.x, v1 = alpha * p.y;
            if (bias) { v0 += beta * bias[col]; v1 += beta * bias[col + 1]; }
            if (do_gelu) {
                v0 = 0.5f * v0 * (1.0f + erff(v0 * 0.7071067811865475f));
                v1 = 0.5f * v1 * (1.0f + erff(v1 * 0.7071067811865475f));
            }
            long idx = (long)row * N + col;
            if (add1) { v0 += cc1 * add1[idx]; v1 += cc1 * add1[idx + 1]; }
            if (add2) { v0 += cc2 * add2[idx]; v1 += cc2 * add2[idx + 1]; }
            C[idx] = v0; C[idx + 1] = v1;
        }
    }
}

// ---------------- embedding gather ----------------
__global__ __launch_bounds__(256)
void embed_kernel(const int* __restrict__ src, const float* __restrict__ W,
                  float* __restrict__ emb)
{
    int t = blockIdx.x, tid = threadIdx.x;
    long row = (long)src[t] * DIM;
#pragma unroll
    for (int k = 0; k < 3; k++)
        emb[(long)t * DIM + tid + k * 256] = W[row + tid + k * 256];
}

// ---------------- attention: scores = scale * Q K^T (per head, 64x64 tiles) ----
__global__ __launch_bounds__(256)
void attn_scores(const float* __restrict__ qkv, float* __restrict__ scores)
{
    __shared__ __align__(16) float Qs[64][64];   // [hd][i]
    __shared__ __align__(16) float Ks[64][64];   // [hd][j]
    int bh = blockIdx.z;
    int b = bh / NH, h = bh % NH;
    int i0 = blockIdx.y * 64;
    int j0 = blockIdx.x * 64;
    int tid = threadIdx.x;
    int tx = tid & 15, ty = tid >> 4;

#pragma unroll
    for (int rep = 0; rep < 4; rep++) {
        int r  = rep * 16 + (tid >> 4);
        int c4 = (tid & 15) * 4;
        float4 q = *(const float4*)&qkv[((long)(b * SEQ + i0 + r)) * (3 * DIM) + h * HD + c4];
        float4 k = *(const float4*)&qkv[((long)(b * SEQ + j0 + r)) * (3 * DIM) + DIM + h * HD + c4];
        Qs[c4+0][r] = q.x; Qs[c4+1][r] = q.y; Qs[c4+2][r] = q.z; Qs[c4+3][r] = q.w;
        Ks[c4+0][r] = k.x; Ks[c4+1][r] = k.y; Ks[c4+2][r] = k.z; Ks[c4+3][r] = k.w;
    }
    __syncthreads();

    float acc[4][4] = {};
#pragma unroll 8
    for (int kk = 0; kk < 64; kk++) {
        float4 qa = *(const float4*)&Qs[kk][ty * 4];
        float4 kb = *(const float4*)&Ks[kk][tx * 4];
        float qr[4] = { qa.x, qa.y, qa.z, qa.w };
        float kr[4] = { kb.x, kb.y, kb.z, kb.w };
#pragma unroll
        for (int i = 0; i < 4; i++)
#pragma unroll
            for (int j = 0; j < 4; j++) acc[i][j] = fmaf(qr[i], kr[j], acc[i][j]);
    }
    const float scale = 0.125f;  // 1/sqrt(64)
    long base = (long)bh * SEQ * SEQ;
#pragma unroll
    for (int i = 0; i < 4; i++)
#pragma unroll
        for (int j = 0; j < 4; j++)
            scores[base + (long)(i0 + ty * 4 + i) * SEQ + j0 + tx * 4 + j] = acc[i][j] * scale;
}

// ---------------- row softmax over 512 ----------------
__global__ __launch_bounds__(256)
void softmax512(float* __restrict__ s)
{
    long base = (long)blockIdx.x * SEQ;
    int tid = threadIdx.x;
    float v0 = s[base + tid], v1 = s[base + 256 + tid];
    __shared__ float red[256];
    red[tid] = fmaxf(v0, v1);
    __syncthreads();
    for (int o = 128; o > 0; o >>= 1) { if (tid < o) red[tid] = fmaxf(red[tid], red[tid + o]); __syncthreads(); }
    float m = red[0];
    __syncthreads();
    float e0 = expf(v0 - m), e1 = expf(v1 - m);
    red[tid] = e0 + e1;
    __syncthreads();
    for (int o = 128; o > 0; o >>= 1) { if (tid < o) red[tid] += red[tid + o]; __syncthreads(); }
    float inv = 1.0f / red[0];
    s[base + tid] = e0 * inv;
    s[base + 256 + tid] = e1 * inv;
}

// ---------------- attention: O = P V (per head) ----------------
__global__ __launch_bounds__(256)
void attn_av(const float* __restrict__ qkv, const float* __restrict__ scores,
             float* __restrict__ attn)
{
    __shared__ __align__(16) float Ps[32][64];   // [j][i]
    __shared__ __align__(16) float Vs[32][64];   // [j][d]
    int bh = blockIdx.z;
    int b = bh / NH, h = bh % NH;
    int i0 = blockIdx.x * 64;
    int tid = threadIdx.x;
    int tx = tid & 15, ty = tid >> 4;
    long sbase = (long)bh * SEQ * SEQ;

    float acc[4][4] = {};
    for (int j0 = 0; j0 < SEQ; j0 += 32) {
        __syncthreads();
#pragma unroll
        for (int rep = 0; rep < 2; rep++) {
            int idx = rep * 256 + tid;
            int r  = idx >> 3;          // i  0..63
            int c4 = (idx & 7) * 4;     // j  0..28
            float4 p = *(const float4*)&scores[sbase + (long)(i0 + r) * SEQ + j0 + c4];
            Ps[c4+0][r] = p.x; Ps[c4+1][r] = p.y; Ps[c4+2][r] = p.z; Ps[c4+3][r] = p.w;
        }
#pragma unroll
        for (int rep = 0; rep < 2; rep++) {
            int idx = rep * 256 + tid;
            int r  = idx >> 4;          // j  0..31
            int c4 = (idx & 15) * 4;    // d
            float4 v = *(const float4*)&qkv[((long)(b * SEQ + j0 + r)) * (3 * DIM) + 2 * DIM + h * HD + c4];
            *(float4*)&Vs[r][c4] = v;
        }
        __syncthreads();
#pragma unroll
        for (int kk = 0; kk < 32; kk++) {
            float4 pa = *(const float4*)&Ps[kk][ty * 4];
            float4 vb = *(const float4*)&Vs[kk][tx * 4];
            float pr[4] = { pa.x, pa.y, pa.z, pa.w };
            float vr[4] = { vb.x, vb.y, vb.z, vb.w };
#pragma unroll
            for (int i = 0; i < 4; i++)
#pragma unroll
                for (int j = 0; j < 4; j++) acc[i][j] = fmaf(pr[i], vr[j], acc[i][j]);
        }
    }
#pragma unroll
    for (int i = 0; i < 4; i++)
#pragma unroll
        for (int j = 0; j < 4; j++)
            attn[((long)(b * SEQ + i0 + ty * 4 + i)) * DIM + h * HD + tx * 4 + j] = acc[i][j];
}

// ---------------- gating: softmax(gate)*(1+0.1*sigmoid(qgate)), renormalized ---
__global__ __launch_bounds__(256)
void gates_kernel(const float* __restrict__ x, const float* __restrict__ gw,
                  const float* __restrict__ gb, const float* __restrict__ qw,
                  const float* __restrict__ qb, float* __restrict__ gates)
{
    int t = blockIdx.x, tid = threadIdx.x;
    __shared__ float xs[DIM];
    __shared__ float lg[NE], lq[NE];
#pragma unroll
    for (int k = 0; k < 3; k++) xs[tid + k * 256] = x[(long)t * DIM + tid + k * 256];
    __syncthreads();
    int w = tid >> 5, lane = tid & 31;   // 8 warps, warp w -> expert w
    float ag = 0.f, aq = 0.f;
    for (int d = lane; d < DIM; d += 32) {
        float xv = xs[d];
        ag = fmaf(xv, gw[w * DIM + d], ag);
        aq = fmaf(xv, qw[w * DIM + d], aq);
    }
    for (int o = 16; o > 0; o >>= 1) {
        ag += __shfl_down_sync(0xffffffffu, ag, o);
        aq += __shfl_down_sync(0xffffffffu, aq, o);
    }
    if (lane == 0) { lg[w] = ag + gb[w]; lq[w] = aq + qb[w]; }
    __syncthreads();
    if (tid == 0) {
        float m = lg[0];
        for (int e = 1; e < NE; e++) m = fmaxf(m, lg[e]);
        float ex[NE], s = 0.f;
        for (int e = 0; e < NE; e++) { ex[e] = expf(lg[e] - m); s += ex[e]; }
        float gg[NE], tot = 0.f;
        for (int e = 0; e < NE; e++) {
            float sm = ex[e] / s;
            float sg = 1.0f / (1.0f + expf(-lq[e]));
            gg[e] = sm * (1.0f + 0.1f * sg);
            tot += gg[e];
        }
        for (int e = 0; e < NE; e++) gates[t * NE + e] = gg[e] / tot;
    }
}

// ---------------- MoE combine + residual + LayerNorm (in-place on x) ----------
__global__ __launch_bounds__(256)
void moe_ln(const float* __restrict__ eo, const float* __restrict__ gates,
            float* __restrict__ x, const float* __restrict__ lng,
            const float* __restrict__ lnb)
{
    int t = blockIdx.x, tid = threadIdx.x;
    __shared__ float gs[NE];
    __shared__ float red[256];
    if (tid < NE) gs[tid] = gates[t * NE + tid];
    __syncthreads();
    float y[3];
    float s = 0.f;
#pragma unroll
    for (int k = 0; k < 3; k++) {
        int d = tid + k * 256;
        float m = 0.f;
#pragma unroll
        for (int e = 0; e < NE; e++)
            m = fmaf(gs[e], eo[((long)e * T_TOK + t) * DIM + d], m);
        float v = x[(long)t * DIM + d] + m;
        y[k] = v; s += v;
    }
    red[tid] = s; __syncthreads();
    for (int o = 128; o > 0; o >>= 1) { if (tid < o) red[tid] += red[tid + o]; __syncthreads(); }
    float mean = red[0] * (1.0f / DIM);
    __syncthreads();
    float s2 = 0.f;
#pragma unroll
    for (int k = 0; k < 3; k++) { float d0 = y[k] - mean; s2 += d0 * d0; }
    red[tid] = s2; __syncthreads();
    for (int o = 128; o > 0; o >>= 1) { if (tid < o) red[tid] += red[tid + o]; __syncthreads(); }
    float inv = rsqrtf(red[0] * (1.0f / DIM) + 1e-5f);
#pragma unroll
    for (int k = 0; k < 3; k++) {
        int d = tid + k * 256;
        x[(long)t * DIM + d] = (y[k] - mean) * inv * lng[d] + lnb[d];
    }
}

// ---------------- host driver ----------------
static void launch_gemm(const float* A, const float* B, const float* bias,
                        const float* add1, const float* add2, const float* qs,
                        float* C, int M, int N, int K,
                        long sA, long sB, long sBias, long sC, int batch,
                        float alpha, float beta, float c1, float c2, int gelu)
{
    dim3 grid(N / 128, M / 128, batch);
    gemm128<<<grid, 256>>>(A, B, bias, add1, add2, qs, C, M, N, K,
                           sA, sB, sBias, sC, alpha, beta, c1, c2, gelu);
}

extern "C" void kernel_launch(void* const* d_in, const int* in_sizes, int n_in,
                              void* d_out, int out_size)
{
    const int*   src       = (const int*)  d_in[0];
    const float* qs        = (const float*)d_in[1];   // quantum_state [1] (device)
    const float* noise     = (const float*)d_in[2];
    const float* embed_W   = (const float*)d_in[3];
    const float* qproj_w   = (const float*)d_in[4];
    const float* qproj_b   = (const float*)d_in[5];
    const float* pos_w     = (const float*)d_in[6];
    const float* pos_b     = (const float*)d_in[7];
    const float* in_proj_w = (const float*)d_in[8];
    const float* in_proj_b = (const float*)d_in[9];
    const float* out_proj_w= (const float*)d_in[10];
    const float* out_proj_b= (const float*)d_in[11];
    const float* ent_w     = (const float*)d_in[12];
    const float* ent_b     = (const float*)d_in[13];
    const float* gate_w    = (const float*)d_in[14];
    const float* gate_b    = (const float*)d_in[15];
    const float* qgate_w   = (const float*)d_in[16];
    const float* qgate_b   = (const float*)d_in[17];
    const float* e_w1      = (const float*)d_in[18];
    const float* e_b1      = (const float*)d_in[19];
    const float* e_w2      = (const float*)d_in[20];
    const float* e_b2      = (const float*)d_in[21];
    const float* ln_g      = (const float*)d_in[22];
    const float* ln_b      = (const float*)d_in[23];
    const float* fc_w      = (const float*)d_in[24];
    const float* fc_b      = (const float*)d_in[25];
    float* out = (float*)d_out;

    float *x, *emb, *tmp, *attn, *qkv, *scores, *hbuf, *eo, *gates;
    cudaGetSymbolAddress((void**)&x,      g_x);
    cudaGetSymbolAddress((void**)&emb,    g_emb);
    cudaGetSymbolAddress((void**)&tmp,    g_tmp);
    cudaGetSymbolAddress((void**)&attn,   g_attn);
    cudaGetSymbolAddress((void**)&qkv,    g_qkv);
    cudaGetSymbolAddress((void**)&scores, g_scores);
    cudaGetSymbolAddress((void**)&hbuf,   g_h);
    cudaGetSymbolAddress((void**)&eo,     g_eo);
    cudaGetSymbolAddress((void**)&gates,  g_gates);

    // --- prologue: quantum embedding + positional mix ---
    embed_kernel<<<T_TOK, 256>>>(src, embed_W, emb);
    // tmp = emb @ qproj^T + qproj_b
    launch_gemm(emb, qproj_w, qproj_b, nullptr, nullptr, nullptr, tmp,
                T_TOK, DIM, DIM, 0, 0, 0, 0, 1, 1.f, 1.f, 0.f, 0.f, 0);
    // x = 0.01*(noise @ pos^T) + pos_b + (1-qs)*emb + qs*tmp
    launch_gemm(noise, pos_w, pos_b, emb, tmp, qs, x,
                T_TOK, DIM, DIM, 0, 0, 0, 0, 1, 0.01f, 1.f, 0.f, 0.f, 0);

    for (int l = 0; l < NL; l++) {
        // qkv = x @ in_proj^T + b
        launch_gemm(x, in_proj_w + (long)l * 3 * DIM * DIM, in_proj_b + l * 3 * DIM,
                    nullptr, nullptr, nullptr, qkv,
                    T_TOK, 3 * DIM, DIM, 0, 0, 0, 0, 1, 1.f, 1.f, 0.f, 0.f, 0);
        attn_scores<<<dim3(SEQ / 64, SEQ / 64, BAT * NH), 256>>>(qkv, scores);
        softmax512<<<BAT * NH * SEQ, 256>>>(scores);
        attn_av<<<dim3(SEQ / 64, 1, BAT * NH), 256>>>(qkv, scores, attn);
        // tmp = attn @ out_proj^T + b
        launch_gemm(attn, out_proj_w + (long)l * DIM * DIM, out_proj_b + l * DIM,
                    nullptr, nullptr, nullptr, tmp,
                    T_TOK, DIM, DIM, 0, 0, 0, 0, 1, 1.f, 1.f, 0.f, 0.f, 0);
        // x = x + tmp + 0.1*(tmp @ ent^T + ent_b)
        launch_gemm(tmp, ent_w + (long)l * DIM * DIM, ent_b + l * DIM,
                    x, tmp, nullptr, x,
                    T_TOK, DIM, DIM, 0, 0, 0, 0, 1, 0.1f, 0.1f, 1.f, 1.f, 0);
        // gates
        gates_kernel<<<T_TOK, 256>>>(x, gate_w + (long)l * NE * DIM, gate_b + l * NE,
                                     qgate_w + (long)l * NE * DIM, qgate_b + l * NE, gates);
        // h[e] = gelu(x @ e_w1[l,e]^T + e_b1[l,e])   (batched over experts)
        launch_gemm(x, e_w1 + (long)l * NE * FF * DIM, e_b1 + (long)l * NE * FF,
                    nullptr, nullptr, nullptr, hbuf,
                    T_TOK, FF, DIM, 0, (long)FF * DIM, FF, (long)T_TOK * FF, NE,
                    1.f, 1.f, 0.f, 0.f, 1);
        // eo[e] = h[e] @ e_w2[l,e]^T + e_b2[l,e]
        launch_gemm(hbuf, e_w2 + (long)l * NE * DIM * FF, e_b2 + (long)l * NE * DIM,
                    nullptr, nullptr, nullptr, eo,
                    T_TOK, DIM, FF, (long)T_TOK * FF, (long)DIM * FF, DIM, (long)T_TOK * DIM, NE,
                    1.f, 1.f, 0.f, 0.f, 0);
        // x = LN(x + sum_e gates[t,e]*eo[e,t,:])
        moe_ln<<<T_TOK, 256>>>(eo, gates, x, ln_g + l * DIM, ln_b + l * DIM);
    }

    // logits = x @ fc_w^T + fc_b
    launch_gemm(x, fc_w, fc_b, nullptr, nullptr, nullptr, out,
                T_TOK, VOC, DIM, 0, 0, 0, 0, 1, 1.f, 1.f, 0.f, 0.f, 0);
}

// round 12
// speedup vs baseline: 1.7134x; 1.6267x over previous
#include <cuda_runtime.h>
#include <cuda_bf16.h>
#include <math.h>

// Problem dims
#define T_TOK 2048   // B*S
#define DIM   768
#define NH    12
#define NL    4
#define NE    8
#define FF    3072
#define VOC   32000
#define SEQ   512
#define BAT   4
#define HD    64

// ---------------- static scratch (allocation-free rule) ----------------
__device__ float g_x   [T_TOK * DIM];
__device__ float g_emb [T_TOK * DIM];
__device__ float g_tmp [T_TOK * DIM];
__device__ float g_attn[T_TOK * DIM];
__device__ float g_qkv [T_TOK * 3 * DIM];
__device__ float g_scores[(size_t)BAT * NH * SEQ * SEQ];
__device__ float g_h  [(size_t)NE * T_TOK * FF];
__device__ float g_eo [(size_t)NE * T_TOK * DIM];
__device__ float g_gates[T_TOK * NE];

// ---------------- bf16 split helpers ----------------
__device__ __forceinline__ void split_store(unsigned* __restrict__ Sh,
                                            unsigned* __restrict__ Sl,
                                            int row, int pos, float x0, float x1)
{
    __nv_bfloat16 h0 = __float2bfloat16(x0), h1 = __float2bfloat16(x1);
    float r0 = x0 - __bfloat162float(h0);
    float r1 = x1 - __bfloat162float(h1);
    __nv_bfloat16 l0 = __float2bfloat16(r0), l1 = __float2bfloat16(r1);
    Sh[row * 16 + pos] = ((unsigned)__bfloat16_as_ushort(h1) << 16) | (unsigned)__bfloat16_as_ushort(h0);
    Sl[row * 16 + pos] = ((unsigned)__bfloat16_as_ushort(l1) << 16) | (unsigned)__bfloat16_as_ushort(l0);
}

__device__ __forceinline__ void mma16816(float* c,
    unsigned a0, unsigned a1, unsigned a2, unsigned a3,
    unsigned b0, unsigned b1)
{
    asm volatile(
        "mma.sync.aligned.m16n8k16.row.col.f32.bf16.bf16.f32 "
        "{%0,%1,%2,%3}, {%4,%5,%6,%7}, {%8,%9}, {%0,%1,%2,%3};"
        : "+f"(c[0]), "+f"(c[1]), "+f"(c[2]), "+f"(c[3])
        : "r"(a0), "r"(a1), "r"(a2), "r"(a3), "r"(b0), "r"(b1));
}

// ---------------- tensor-core GEMM (bf16x3 split, fp32-grade accuracy) ----
// C[m,n] = f(alpha*sum_k A[m,k]*B[n,k] + beta*bias[n]) + c1*add1 + c2*add2
// If qsp != null: c1 = 1-*qsp, c2 = *qsp. f = exact GELU if do_gelu.
// Batched via blockIdx.z. Requires M%128==0, N%128==0, K%32==0.
__global__ __launch_bounds__(256, 1)
void gemm_bf16x3(const float* __restrict__ A, const float* __restrict__ B,
                 const float* __restrict__ bias,
                 const float* __restrict__ add1, const float* __restrict__ add2,
                 const float* __restrict__ qsp,
                 float* __restrict__ C,
                 int M, int N, int K,
                 long sA, long sB, long sBias, long sC,
                 float alpha, float beta, float c1, float c2, int do_gelu)
{
    // bf16 hi/lo tiles, 128 rows x 32 k (16 u32 per row), k-pair-permuted
    __shared__ __align__(16) unsigned Ah[128 * 16];
    __shared__ __align__(16) unsigned Al[128 * 16];
    __shared__ __align__(16) unsigned Bh[128 * 16];
    __shared__ __align__(16) unsigned Bl[128 * 16];

    const int bz = blockIdx.z;
    A += (long)bz * sA;
    B += (long)bz * sB;
    C += (long)bz * sC;
    if (bias) bias += (long)bz * sBias;

    const int n0 = blockIdx.x * 128;
    const int m0 = blockIdx.y * 128;
    const int tid = threadIdx.x;

    // global loader coords: 32 rows x 8 float4-cols per rep, 4 reps
    const int lr = tid >> 3;       // 0..31
    const int lc = tid & 7;        // float4 col (k = lc*4)
    const int p0 = lc * 2, p1 = lc * 2 + 1;                // bf16x2 pair indices
    const int pos0 = ((p0 & 3) << 2) | (p0 >> 2);          // permuted positions
    const int pos1 = ((p1 & 3) << 2) | (p1 >> 2);

    // mma coords
    const int lane = tid & 31, wid = tid >> 5;
    const int wm = wid >> 2, wn = wid & 3;   // 2 x 4 warp grid, warp tile 64x32
    const int g = lane >> 2, tg = lane & 3;

    float acc[4][4][4];
#pragma unroll
    for (int i = 0; i < 4; i++)
#pragma unroll
        for (int j = 0; j < 4; j++)
#pragma unroll
            for (int r = 0; r < 4; r++) acc[i][j][r] = 0.f;

    float4 ra[4], rb[4];
    const int nk = K >> 5;

    auto load_g = [&](int k0) {
#pragma unroll
        for (int rep = 0; rep < 4; rep++) {
            ra[rep] = *(const float4*)&A[(long)(m0 + lr + rep * 32) * K + k0 + lc * 4];
            rb[rep] = *(const float4*)&B[(long)(n0 + lr + rep * 32) * K + k0 + lc * 4];
        }
    };
    auto store_s = [&]() {
#pragma unroll
        for (int rep = 0; rep < 4; rep++) {
            int row = lr + rep * 32;
            split_store(Ah, Al, row, pos0, ra[rep].x, ra[rep].y);
            split_store(Ah, Al, row, pos1, ra[rep].z, ra[rep].w);
            split_store(Bh, Bl, row, pos0, rb[rep].x, rb[rep].y);
            split_store(Bh, Bl, row, pos1, rb[rep].z, rb[rep].w);
        }
    };
    auto compute = [&]() {
        const uint4* A4h = (const uint4*)Ah;
        const uint4* A4l = (const uint4*)Al;
        const uint4* B4h = (const uint4*)Bh;
        const uint4* B4l = (const uint4*)Bl;
        uint4 vbh[4], vbl[4];
#pragma unroll
        for (int nf = 0; nf < 4; nf++) {
            int n = wn * 32 + nf * 8 + g;
            vbh[nf] = B4h[n * 4 + tg];
            vbl[nf] = B4l[n * 4 + tg];
        }
#pragma unroll
        for (int mf = 0; mf < 4; mf++) {
            int r0 = wm * 64 + mf * 16 + g;
            uint4 ah0 = A4h[r0 * 4 + tg];
            uint4 ah8 = A4h[(r0 + 8) * 4 + tg];
            uint4 al0 = A4l[r0 * 4 + tg];
            uint4 al8 = A4l[(r0 + 8) * 4 + tg];
#pragma unroll
            for (int nf = 0; nf < 4; nf++) {
                float* c = acc[mf][nf];
                // k-step 0 (k 0..15): hi*hi + hi*lo + lo*hi
                mma16816(c, ah0.x, ah8.x, ah0.y, ah8.y, vbh[nf].x, vbh[nf].y);
                mma16816(c, ah0.x, ah8.x, ah0.y, ah8.y, vbl[nf].x, vbl[nf].y);
                mma16816(c, al0.x, al8.x, al0.y, al8.y, vbh[nf].x, vbh[nf].y);
                // k-step 1 (k 16..31)
                mma16816(c, ah0.z, ah8.z, ah0.w, ah8.w, vbh[nf].z, vbh[nf].w);
                mma16816(c, ah0.z, ah8.z, ah0.w, ah8.w, vbl[nf].z, vbl[nf].w);
                mma16816(c, al0.z, al8.z, al0.w, al8.w, vbh[nf].z, vbh[nf].w);
            }
        }
    };

    load_g(0);
    store_s();
    __syncthreads();
    for (int kt = 1; kt < nk; kt++) {
        load_g(kt << 5);          // prefetch next tile into regs
        compute();                // compute on current smem tile
        __syncthreads();
        store_s();
        __syncthreads();
    }
    compute();

    // ---- fused epilogue ----
    float cc1 = c1, cc2 = c2;
    if (qsp) { float q = *qsp; cc1 = 1.0f - q; cc2 = q; }

#pragma unroll
    for (int mf = 0; mf < 4; mf++) {
#pragma unroll
        for (int nf = 0; nf < 4; nf++) {
            int row = m0 + wm * 64 + mf * 16 + g;
            int col = n0 + wn * 32 + nf * 8 + 2 * tg;
            float* c = acc[mf][nf];
#pragma unroll
            for (int half = 0; half < 2; half++) {
                int rr = row + half * 8;
                float v0 = alpha * c[half * 2 + 0];
                float v1 = alpha * c[half * 2 + 1];
                if (bias) { v0 += beta * bias[col]; v1 += beta * bias[col + 1]; }
                if (do_gelu) {
                    v0 = 0.5f * v0 * (1.0f + erff(v0 * 0.7071067811865475f));
                    v1 = 0.5f * v1 * (1.0f + erff(v1 * 0.7071067811865475f));
                }
                long idx = (long)rr * N + col;
                if (add1) { v0 += cc1 * add1[idx]; v1 += cc1 * add1[idx + 1]; }
                if (add2) { v0 += cc2 * add2[idx]; v1 += cc2 * add2[idx + 1]; }
                C[idx] = v0; C[idx + 1] = v1;
            }
        }
    }
}

// ---------------- embedding gather ----------------
__global__ __launch_bounds__(256)
void embed_kernel(const int* __restrict__ src, const float* __restrict__ W,
                  float* __restrict__ emb)
{
    int t = blockIdx.x, tid = threadIdx.x;
    long row = (long)src[t] * DIM;
#pragma unroll
    for (int k = 0; k < 3; k++)
        emb[(long)t * DIM + tid + k * 256] = W[row + tid + k * 256];
}

// ---------------- attention: scores = scale * Q K^T (per head, 64x64 tiles) ----
__global__ __launch_bounds__(256)
void attn_scores(const float* __restrict__ qkv, float* __restrict__ scores)
{
    __shared__ __align__(16) float Qs[64][64];   // [hd][i]
    __shared__ __align__(16) float Ks[64][64];   // [hd][j]
    int bh = blockIdx.z;
    int b = bh / NH, h = bh % NH;
    int i0 = blockIdx.y * 64;
    int j0 = blockIdx.x * 64;
    int tid = threadIdx.x;
    int tx = tid & 15, ty = tid >> 4;

#pragma unroll
    for (int rep = 0; rep < 4; rep++) {
        int r  = rep * 16 + (tid >> 4);
        int c4 = (tid & 15) * 4;
        float4 q = *(const float4*)&qkv[((long)(b * SEQ + i0 + r)) * (3 * DIM) + h * HD + c4];
        float4 k = *(const float4*)&qkv[((long)(b * SEQ + j0 + r)) * (3 * DIM) + DIM + h * HD + c4];
        Qs[c4+0][r] = q.x; Qs[c4+1][r] = q.y; Qs[c4+2][r] = q.z; Qs[c4+3][r] = q.w;
        Ks[c4+0][r] = k.x; Ks[c4+1][r] = k.y; Ks[c4+2][r] = k.z; Ks[c4+3][r] = k.w;
    }
    __syncthreads();

    float acc[4][4] = {};
#pragma unroll 8
    for (int kk = 0; kk < 64; kk++) {
        float4 qa = *(const float4*)&Qs[kk][ty * 4];
        float4 kb = *(const float4*)&Ks[kk][tx * 4];
        float qr[4] = { qa.x, qa.y, qa.z, qa.w };
        float kr[4] = { kb.x, kb.y, kb.z, kb.w };
#pragma unroll
        for (int i = 0; i < 4; i++)
#pragma unroll
            for (int j = 0; j < 4; j++) acc[i][j] = fmaf(qr[i], kr[j], acc[i][j]);
    }
    const float scale = 0.125f;  // 1/sqrt(64)
    long base = (long)bh * SEQ * SEQ;
#pragma unroll
    for (int i = 0; i < 4; i++)
#pragma unroll
        for (int j = 0; j < 4; j++)
            scores[base + (long)(i0 + ty * 4 + i) * SEQ + j0 + tx * 4 + j] = acc[i][j] * scale;
}

// ---------------- row softmax over 512 ----------------
__global__ __launch_bounds__(256)
void softmax512(float* __restrict__ s)
{
    long base = (long)blockIdx.x * SEQ;
    int tid = threadIdx.x;
    float v0 = s[base + tid], v1 = s[base + 256 + tid];
    __shared__ float red[256];
    red[tid] = fmaxf(v0, v1);
    __syncthreads();
    for (int o = 128; o > 0; o >>= 1) { if (tid < o) red[tid] = fmaxf(red[tid], red[tid + o]); __syncthreads(); }
    float m = red[0];
    __syncthreads();
    float e0 = expf(v0 - m), e1 = expf(v1 - m);
    red[tid] = e0 + e1;
    __syncthreads();
    for (int o = 128; o > 0; o >>= 1) { if (tid < o) red[tid] += red[tid + o]; __syncthreads(); }
    float inv = 1.0f / red[0];
    s[base + tid] = e0 * inv;
    s[base + 256 + tid] = e1 * inv;
}

// ---------------- attention: O = P V (per head) ----------------
__global__ __launch_bounds__(256)
void attn_av(const float* __restrict__ qkv, const float* __restrict__ scores,
             float* __restrict__ attn)
{
    __shared__ __align__(16) float Ps[32][64];   // [j][i]
    __shared__ __align__(16) float Vs[32][64];   // [j][d]
    int bh = blockIdx.z;
    int b = bh / NH, h = bh % NH;
    int i0 = blockIdx.x * 64;
    int tid = threadIdx.x;
    int tx = tid & 15, ty = tid >> 4;
    long sbase = (long)bh * SEQ * SEQ;

    float acc[4][4] = {};
    for (int j0 = 0; j0 < SEQ; j0 += 32) {
        __syncthreads();
#pragma unroll
        for (int rep = 0; rep < 2; rep++) {
            int idx = rep * 256 + tid;
            int r  = idx >> 3;          // i  0..63
            int c4 = (idx & 7) * 4;     // j  0..28
            float4 p = *(const float4*)&scores[sbase + (long)(i0 + r) * SEQ + j0 + c4];
            Ps[c4+0][r] = p.x; Ps[c4+1][r] = p.y; Ps[c4+2][r] = p.z; Ps[c4+3][r] = p.w;
        }
#pragma unroll
        for (int rep = 0; rep < 2; rep++) {
            int idx = rep * 256 + tid;
            int r  = idx >> 4;          // j  0..31
            int c4 = (idx & 15) * 4;    // d
            float4 v = *(const float4*)&qkv[((long)(b * SEQ + j0 + r)) * (3 * DIM) + 2 * DIM + h * HD + c4];
            *(float4*)&Vs[r][c4] = v;
        }
        __syncthreads();
#pragma unroll
        for (int kk = 0; kk < 32; kk++) {
            float4 pa = *(const float4*)&Ps[kk][ty * 4];
            float4 vb = *(const float4*)&Vs[kk][tx * 4];
            float pr[4] = { pa.x, pa.y, pa.z, pa.w };
            float vr[4] = { vb.x, vb.y, vb.z, vb.w };
#pragma unroll
            for (int i = 0; i < 4; i++)
#pragma unroll
                for (int j = 0; j < 4; j++) acc[i][j] = fmaf(pr[i], vr[j], acc[i][j]);
        }
    }
#pragma unroll
    for (int i = 0; i < 4; i++)
#pragma unroll
        for (int j = 0; j < 4; j++)
            attn[((long)(b * SEQ + i0 + ty * 4 + i)) * DIM + h * HD + tx * 4 + j] = acc[i][j];
}

// ---------------- gating: softmax(gate)*(1+0.1*sigmoid(qgate)), renormalized ---
__global__ __launch_bounds__(256)
void gates_kernel(const float* __restrict__ x, const float* __restrict__ gw,
                  const float* __restrict__ gb, const float* __restrict__ qw,
                  const float* __restrict__ qb, float* __restrict__ gates)
{
    int t = blockIdx.x, tid = threadIdx.x;
    __shared__ float xs[DIM];
    __shared__ float lg[NE], lq[NE];
#pragma unroll
    for (int k = 0; k < 3; k++) xs[tid + k * 256] = x[(long)t * DIM + tid + k * 256];
    __syncthreads();
    int w = tid >> 5, lane = tid & 31;   // 8 warps, warp w -> expert w
    float ag = 0.f, aq = 0.f;
    for (int d = lane; d < DIM; d += 32) {
        float xv = xs[d];
        ag = fmaf(xv, gw[w * DIM + d], ag);
        aq = fmaf(xv, qw[w * DIM + d], aq);
    }
    for (int o = 16; o > 0; o >>= 1) {
        ag += __shfl_down_sync(0xffffffffu, ag, o);
        aq += __shfl_down_sync(0xffffffffu, aq, o);
    }
    if (lane == 0) { lg[w] = ag + gb[w]; lq[w] = aq + qb[w]; }
    __syncthreads();
    if (tid == 0) {
        float m = lg[0];
        for (int e = 1; e < NE; e++) m = fmaxf(m, lg[e]);
        float ex[NE], s = 0.f;
        for (int e = 0; e < NE; e++) { ex[e] = expf(lg[e] - m); s += ex[e]; }
        float gg[NE], tot = 0.f;
        for (int e = 0; e < NE; e++) {
            float sm = ex[e] / s;
            float sg = 1.0f / (1.0f + expf(-lq[e]));
            gg[e] = sm * (1.0f + 0.1f * sg);
            tot += gg[e];
        }
        for (int e = 0; e < NE; e++) gates[t * NE + e] = gg[e] / tot;
    }
}

// ---------------- MoE combine + residual + LayerNorm (in-place on x) ----------
__global__ __launch_bounds__(256)
void moe_ln(const float* __restrict__ eo, const float* __restrict__ gates,
            float* __restrict__ x, const float* __restrict__ lng,
            const float* __restrict__ lnb)
{
    int t = blockIdx.x, tid = threadIdx.x;
    __shared__ float gs[NE];
    __shared__ float red[256];
    if (tid < NE) gs[tid] = gates[t * NE + tid];
    __syncthreads();
    float y[3];
    float s = 0.f;
#pragma unroll
    for (int k = 0; k < 3; k++) {
        int d = tid + k * 256;
        float m = 0.f;
#pragma unroll
        for (int e = 0; e < NE; e++)
            m = fmaf(gs[e], eo[((long)e * T_TOK + t) * DIM + d], m);
        float v = x[(long)t * DIM + d] + m;
        y[k] = v; s += v;
    }
    red[tid] = s; __syncthreads();
    for (int o = 128; o > 0; o >>= 1) { if (tid < o) red[tid] += red[tid + o]; __syncthreads(); }
    float mean = red[0] * (1.0f / DIM);
    __syncthreads();
    float s2 = 0.f;
#pragma unroll
    for (int k = 0; k < 3; k++) { float d0 = y[k] - mean; s2 += d0 * d0; }
    red[tid] = s2; __syncthreads();
    for (int o = 128; o > 0; o >>= 1) { if (tid < o) red[tid] += red[tid + o]; __syncthreads(); }
    float inv = rsqrtf(red[0] * (1.0f / DIM) + 1e-5f);
#pragma unroll
    for (int k = 0; k < 3; k++) {
        int d = tid + k * 256;
        x[(long)t * DIM + d] = (y[k] - mean) * inv * lng[d] + lnb[d];
    }
}

// ---------------- host driver ----------------
static void launch_gemm(const float* A, const float* B, const float* bias,
                        const float* add1, const float* add2, const float* qs,
                        float* C, int M, int N, int K,
                        long sA, long sB, long sBias, long sC, int batch,
                        float alpha, float beta, float c1, float c2, int gelu)
{
    dim3 grid(N / 128, M / 128, batch);
    gemm_bf16x3<<<grid, 256>>>(A, B, bias, add1, add2, qs, C, M, N, K,
                               sA, sB, sBias, sC, alpha, beta, c1, c2, gelu);
}

extern "C" void kernel_launch(void* const* d_in, const int* in_sizes, int n_in,
                              void* d_out, int out_size)
{
    const int*   src       = (const int*)  d_in[0];
    const float* qs        = (const float*)d_in[1];   // quantum_state [1] (device)
    const float* noise     = (const float*)d_in[2];
    const float* embed_W   = (const float*)d_in[3];
    const float* qproj_w   = (const float*)d_in[4];
    const float* qproj_b   = (const float*)d_in[5];
    const float* pos_w     = (const float*)d_in[6];
    const float* pos_b     = (const float*)d_in[7];
    const float* in_proj_w = (const float*)d_in[8];
    const float* in_proj_b = (const float*)d_in[9];
    const float* out_proj_w= (const float*)d_in[10];
    const float* out_proj_b= (const float*)d_in[11];
    const float* ent_w     = (const float*)d_in[12];
    const float* ent_b     = (const float*)d_in[13];
    const float* gate_w    = (const float*)d_in[14];
    const float* gate_b    = (const float*)d_in[15];
    const float* qgate_w   = (const float*)d_in[16];
    const float* qgate_b   = (const float*)d_in[17];
    const float* e_w1      = (const float*)d_in[18];
    const float* e_b1      = (const float*)d_in[19];
    const float* e_w2      = (const float*)d_in[20];
    const float* e_b2      = (const float*)d_in[21];
    const float* ln_g      = (const float*)d_in[22];
    const float* ln_b      = (const float*)d_in[23];
    const float* fc_w      = (const float*)d_in[24];
    const float* fc_b      = (const float*)d_in[25];
    float* out = (float*)d_out;

    float *x, *emb, *tmp, *attn, *qkv, *scores, *hbuf, *eo, *gates;
    cudaGetSymbolAddress((void**)&x,      g_x);
    cudaGetSymbolAddress((void**)&emb,    g_emb);
    cudaGetSymbolAddress((void**)&tmp,    g_tmp);
    cudaGetSymbolAddress((void**)&attn,   g_attn);
    cudaGetSymbolAddress((void**)&qkv,    g_qkv);
    cudaGetSymbolAddress((void**)&scores, g_scores);
    cudaGetSymbolAddress((void**)&hbuf,   g_h);
    cudaGetSymbolAddress((void**)&eo,     g_eo);
    cudaGetSymbolAddress((void**)&gates,  g_gates);

    // --- prologue: quantum embedding + positional mix ---
    embed_kernel<<<T_TOK, 256>>>(src, embed_W, emb);
    // tmp = emb @ qproj^T + qproj_b
    launch_gemm(emb, qproj_w, qproj_b, nullptr, nullptr, nullptr, tmp,
                T_TOK, DIM, DIM, 0, 0, 0, 0, 1, 1.f, 1.f, 0.f, 0.f, 0);
    // x = 0.01*(noise @ pos^T) + pos_b + (1-qs)*emb + qs*tmp
    launch_gemm(noise, pos_w, pos_b, emb, tmp, qs, x,
                T_TOK, DIM, DIM, 0, 0, 0, 0, 1, 0.01f, 1.f, 0.f, 0.f, 0);

    for (int l = 0; l < NL; l++) {
        // qkv = x @ in_proj^T + b
        launch_gemm(x, in_proj_w + (long)l * 3 * DIM * DIM, in_proj_b + l * 3 * DIM,
                    nullptr, nullptr, nullptr, qkv,
                    T_TOK, 3 * DIM, DIM, 0, 0, 0, 0, 1, 1.f, 1.f, 0.f, 0.f, 0);
        attn_scores<<<dim3(SEQ / 64, SEQ / 64, BAT * NH), 256>>>(qkv, scores);
        softmax512<<<BAT * NH * SEQ, 256>>>(scores);
        attn_av<<<dim3(SEQ / 64, 1, BAT * NH), 256>>>(qkv, scores, attn);
        // tmp = attn @ out_proj^T + b
        launch_gemm(attn, out_proj_w + (long)l * DIM * DIM, out_proj_b + l * DIM,
                    nullptr, nullptr, nullptr, tmp,
                    T_TOK, DIM, DIM, 0, 0, 0, 0, 1, 1.f, 1.f, 0.f, 0.f, 0);
        // x = x + tmp + 0.1*(tmp @ ent^T + ent_b)
        launch_gemm(tmp, ent_w + (long)l * DIM * DIM, ent_b + l * DIM,
                    x, tmp, nullptr, x,
                    T_TOK, DIM, DIM, 0, 0, 0, 0, 1, 0.1f, 0.1f, 1.f, 1.f, 0);
        // gates
        gates_kernel<<<T_TOK, 256>>>(x, gate_w + (long)l * NE * DIM, gate_b + l * NE,
                                     qgate_w + (long)l * NE * DIM, qgate_b + l * NE, gates);
        // h[e] = gelu(x @ e_w1[l,e]^T + e_b1[l,e])   (batched over experts)
        launch_gemm(x, e_w1 + (long)l * NE * FF * DIM, e_b1 + (long)l * NE * FF,
                    nullptr, nullptr, nullptr, hbuf,
                    T_TOK, FF, DIM, 0, (long)FF * DIM, FF, (long)T_TOK * FF, NE,
                    1.f, 1.f, 0.f, 0.f, 1);
        // eo[e] = h[e] @ e_w2[l,e]^T + e_b2[l,e]
        launch_gemm(hbuf, e_w2 + (long)l * NE * DIM * FF, e_b2 + (long)l * NE * DIM,
                    nullptr, nullptr, nullptr, eo,
                    T_TOK, DIM, FF, (long)T_TOK * FF, (long)DIM * FF, DIM, (long)T_TOK * DIM, NE,
                    1.f, 1.f, 0.f, 0.f, 0);
        // x = LN(x + sum_e gates[t,e]*eo[e,t,:])
        moe_ln<<<T_TOK, 256>>>(eo, gates, x, ln_g + l * DIM, ln_b + l * DIM);
    }

    // logits = x @ fc_w^T + fc_b
    launch_gemm(x, fc_w, fc_b, nullptr, nullptr, nullptr, out,
                T_TOK, VOC, DIM, 0, 0, 0, 0, 1, 1.f, 1.f, 0.f, 0.f, 0);
}

// round 13
// speedup vs baseline: 1.9567x; 1.1419x over previous
#include <cuda_runtime.h>
#include <cuda_bf16.h>
#include <math.h>

// Problem dims
#define T_TOK 2048   // B*S
#define DIM   768
#define NH    12
#define NL    4
#define NE    8
#define FF    3072
#define VOC   32000
#define SEQ   512
#define BAT   4
#define HD    64

// ---------------- static fp32 scratch ----------------
__device__ float g_x   [T_TOK * DIM];
__device__ float g_emb [T_TOK * DIM];
__device__ float g_tmp [T_TOK * DIM];
__device__ float g_attn[T_TOK * DIM];
__device__ float g_qkv [T_TOK * 3 * DIM];
__device__ float g_scores[(size_t)BAT * NH * SEQ * SEQ];
__device__ float g_eo [(size_t)NE * T_TOK * DIM];
__device__ float g_gates[T_TOK * NE];

// ---------------- split bf16 hi/lo buffers (u32 = packed bf16x2) --------
// layout: [row][chunk(kt)][pos 0..15] with pos = ((p&3)<<2)|(p>>2), p = (k%32)/2
__device__ unsigned w_qproj_h[294912],   w_qproj_l[294912];
__device__ unsigned w_pos_h  [294912],   w_pos_l  [294912];
__device__ unsigned w_inp_h  [3538944],  w_inp_l  [3538944];
__device__ unsigned w_outp_h [1179648],  w_outp_l [1179648];
__device__ unsigned w_ent_h  [1179648],  w_ent_l  [1179648];
__device__ unsigned w_e1_h   [37748736], w_e1_l   [37748736];
__device__ unsigned w_e2_h   [37748736], w_e2_l   [37748736];
__device__ unsigned w_fc_h   [12288000], w_fc_l   [12288000];
__device__ unsigned s_x_h    [786432],   s_x_l    [786432];
__device__ unsigned s_h_h    [25165824], s_h_l    [25165824];

// ---------------- fp32 -> split-permuted bf16 hi/lo converter ----------
__global__ __launch_bounds__(256)
void split_permute(const float* __restrict__ src, unsigned* __restrict__ hi,
                   unsigned* __restrict__ lo, long n4)
{
    long i = (long)blockIdx.x * 256 + threadIdx.x;
    if (i >= n4) return;
    float4 v = ((const float4*)src)[i];
    long k = i * 4;
    long chunk = k >> 5;
    int q = (int)(k & 31);
    int p0 = q >> 1, p1 = p0 + 1;
    int pos0 = ((p0 & 3) << 2) | (p0 >> 2);
    int pos1 = ((p1 & 3) << 2) | (p1 >> 2);

    __nv_bfloat16 hx = __float2bfloat16(v.x), hy = __float2bfloat16(v.y);
    __nv_bfloat16 hz = __float2bfloat16(v.z), hw = __float2bfloat16(v.w);
    __nv_bfloat16 lx = __float2bfloat16(v.x - __bfloat162float(hx));
    __nv_bfloat16 ly = __float2bfloat16(v.y - __bfloat162float(hy));
    __nv_bfloat16 lz = __float2bfloat16(v.z - __bfloat162float(hz));
    __nv_bfloat16 lw = __float2bfloat16(v.w - __bfloat162float(hw));

    hi[chunk * 16 + pos0] = ((unsigned)__bfloat16_as_ushort(hy) << 16) | __bfloat16_as_ushort(hx);
    hi[chunk * 16 + pos1] = ((unsigned)__bfloat16_as_ushort(hw) << 16) | __bfloat16_as_ushort(hz);
    lo[chunk * 16 + pos0] = ((unsigned)__bfloat16_as_ushort(ly) << 16) | __bfloat16_as_ushort(lx);
    lo[chunk * 16 + pos1] = ((unsigned)__bfloat16_as_ushort(lw) << 16) | __bfloat16_as_ushort(lz);
}

// ---------------- mma + cp.async helpers ----------------
__device__ __forceinline__ void mma16816(float* c,
    unsigned a0, unsigned a1, unsigned a2, unsigned a3,
    unsigned b0, unsigned b1)
{
    asm volatile(
        "mma.sync.aligned.m16n8k16.row.col.f32.bf16.bf16.f32 "
        "{%0,%1,%2,%3}, {%4,%5,%6,%7}, {%8,%9}, {%0,%1,%2,%3};"
        : "+f"(c[0]), "+f"(c[1]), "+f"(c[2]), "+f"(c[3])
        : "r"(a0), "r"(a1), "r"(a2), "r"(a3), "r"(b0), "r"(b1));
}
__device__ __forceinline__ void cpa16(unsigned saddr, const void* gaddr) {
    asm volatile("cp.async.ca.shared.global [%0], [%1], 16;" :: "r"(saddr), "l"(gaddr));
}
#define CP_COMMIT() asm volatile("cp.async.commit_group;")
#define CP_WAIT(n)  asm volatile("cp.async.wait_group %0;" :: "n"(n))

// ---------------- tensor-core GEMM on pre-split operands ----------------
// C[m,n] = f(alpha * sum_k A[m,k]*B[n,k] + beta*bias[n]) + c1*add1 + c2*add2
// If qsp: c1=1-*qsp, c2=*qsp. f = exact GELU if do_gelu.
// If Chi/Clo set: write split-permuted bf16 hi/lo instead of fp32 C.
// Strides sA,sB,sBias,sC in ELEMENTS per blockIdx.z batch.
__global__ __launch_bounds__(256, 1)
void gemm_sp(const unsigned* __restrict__ Ah_g, const unsigned* __restrict__ Al_g,
             const unsigned* __restrict__ Bh_g, const unsigned* __restrict__ Bl_g,
             const float* __restrict__ bias,
             const float* __restrict__ add1, const float* __restrict__ add2,
             const float* __restrict__ qsp,
             float* __restrict__ C, unsigned* __restrict__ Chi, unsigned* __restrict__ Clo,
             int M, int N, int K,
             long sA, long sB, long sBias, long sC,
             float alpha, float beta, float c1, float c2, int do_gelu)
{
    extern __shared__ unsigned smem_u[];   // 2 bufs x 4 arrays x 2048 u32 = 64KB

    const int bz = blockIdx.z;
    Ah_g += bz * (sA >> 1);  Al_g += bz * (sA >> 1);
    Bh_g += bz * (sB >> 1);  Bl_g += bz * (sB >> 1);
    if (C)    C    += bz * sC;
    if (Chi)  { Chi += bz * (sC >> 1); Clo += bz * (sC >> 1); }
    if (bias) bias += bz * sBias;

    const int n0 = blockIdx.x * 128;
    const int m0 = blockIdx.y * 128;
    const int tid = threadIdx.x;
    const int KC = K >> 5;          // 32-k chunks per row
    const int nk = KC;

    // loader: thread copies segment s = tid + j*256 (j=0,1) of each array.
    // segment s -> row = s>>2, part = s&3 (16B = 4 u32)
    const int lrow = tid >> 2;
    const int lpart = tid & 3;
    long aoff[2], boff[2];
    aoff[0] = ((long)(m0 + lrow)      * KC) * 16 + lpart * 4;
    aoff[1] = ((long)(m0 + lrow + 64) * KC) * 16 + lpart * 4;
    boff[0] = ((long)(n0 + lrow)      * KC) * 16 + lpart * 4;
    boff[1] = ((long)(n0 + lrow + 64) * KC) * 16 + lpart * 4;

    unsigned sbase = (unsigned)__cvta_generic_to_shared(smem_u);

    auto issue = [&](int kt, int b) {
        long ko = (long)kt * 16;
        unsigned sb = sbase + b * 32768;
#pragma unroll
        for (int j = 0; j < 2; j++) {
            unsigned so = sb + tid * 16 + j * 4096;
            cpa16(so +     0, Ah_g + aoff[j] + ko);
            cpa16(so +  8192, Al_g + aoff[j] + ko);
            cpa16(so + 16384, Bh_g + boff[j] + ko);
            cpa16(so + 24576, Bl_g + boff[j] + ko);
        }
    };

    // mma coords
    const int lane = tid & 31, wid = tid >> 5;
    const int wm = wid >> 2, wn = wid & 3;   // 2 x 4 warp grid, warp tile 64x32
    const int g = lane >> 2, tg = lane & 3;

    float acc[4][4][4];
#pragma unroll
    for (int i = 0; i < 4; i++)
#pragma unroll
        for (int j = 0; j < 4; j++)
#pragma unroll
            for (int r = 0; r < 4; r++) acc[i][j][r] = 0.f;

    auto compute = [&](int b) {
        const unsigned* base = smem_u + b * 8192;
        const uint4* A4h = (const uint4*)(base);
        const uint4* A4l = (const uint4*)(base + 2048);
        const uint4* B4h = (const uint4*)(base + 4096);
        const uint4* B4l = (const uint4*)(base + 6144);
        uint4 vbh[4], vbl[4];
#pragma unroll
        for (int nf = 0; nf < 4; nf++) {
            int n = wn * 32 + nf * 8 + g;
            vbh[nf] = B4h[n * 4 + tg];
            vbl[nf] = B4l[n * 4 + tg];
        }
#pragma unroll
        for (int mf = 0; mf < 4; mf++) {
            int r0 = wm * 64 + mf * 16 + g;
            uint4 ah0 = A4h[r0 * 4 + tg];
            uint4 ah8 = A4h[(r0 + 8) * 4 + tg];
            uint4 al0 = A4l[r0 * 4 + tg];
            uint4 al8 = A4l[(r0 + 8) * 4 + tg];
#pragma unroll
            for (int nf = 0; nf < 4; nf++) {
                float* c = acc[mf][nf];
                // k-step 0 (k 0..15): hi*hi + hi*lo + lo*hi
                mma16816(c, ah0.x, ah8.x, ah0.y, ah8.y, vbh[nf].x, vbh[nf].y);
                mma16816(c, ah0.x, ah8.x, ah0.y, ah8.y, vbl[nf].x, vbl[nf].y);
                mma16816(c, al0.x, al8.x, al0.y, al8.y, vbh[nf].x, vbh[nf].y);
                // k-step 1 (k 16..31)
                mma16816(c, ah0.z, ah8.z, ah0.w, ah8.w, vbh[nf].z, vbh[nf].w);
                mma16816(c, ah0.z, ah8.z, ah0.w, ah8.w, vbl[nf].z, vbl[nf].w);
                mma16816(c, al0.z, al8.z, al0.w, al8.w, vbh[nf].z, vbh[nf].w);
            }
        }
    };

    issue(0, 0);
    CP_COMMIT();
    for (int kt = 0; kt < nk; kt++) {
        if (kt + 1 < nk) {
            issue(kt + 1, (kt + 1) & 1);
            CP_COMMIT();
            CP_WAIT(1);
        } else {
            CP_WAIT(0);
        }
        __syncthreads();
        compute(kt & 1);
        __syncthreads();
    }

    // ---- fused epilogue ----
    float cc1 = c1, cc2 = c2;
    if (qsp) { float q = *qsp; cc1 = 1.0f - q; cc2 = q; }

#pragma unroll
    for (int mf = 0; mf < 4; mf++) {
#pragma unroll
        for (int nf = 0; nf < 4; nf++) {
            int row = m0 + wm * 64 + mf * 16 + g;
            int col = n0 + wn * 32 + nf * 8 + 2 * tg;
            float* c = acc[mf][nf];
#pragma unroll
            for (int half = 0; half < 2; half++) {
                int rr = row + half * 8;
                float v0 = alpha * c[half * 2 + 0];
                float v1 = alpha * c[half * 2 + 1];
                if (bias) { v0 += beta * bias[col]; v1 += beta * bias[col + 1]; }
                if (do_gelu) {
                    v0 = 0.5f * v0 * (1.0f + erff(v0 * 0.7071067811865475f));
                    v1 = 0.5f * v1 * (1.0f + erff(v1 * 0.7071067811865475f));
                }
                if (Chi) {
                    long chunk = (long)rr * (N >> 5) + (col >> 5);
                    int p = (col & 31) >> 1;
                    int pos = ((p & 3) << 2) | (p >> 2);
                    __nv_bfloat16 h0 = __float2bfloat16(v0), h1 = __float2bfloat16(v1);
                    __nv_bfloat16 l0 = __float2bfloat16(v0 - __bfloat162float(h0));
                    __nv_bfloat16 l1 = __float2bfloat16(v1 - __bfloat162float(h1));
                    Chi[chunk * 16 + pos] = ((unsigned)__bfloat16_as_ushort(h1) << 16) | __bfloat16_as_ushort(h0);
                    Clo[chunk * 16 + pos] = ((unsigned)__bfloat16_as_ushort(l1) << 16) | __bfloat16_as_ushort(l0);
                } else {
                    long idx = (long)rr * N + col;
                    if (add1) { v0 += cc1 * add1[idx]; v1 += cc1 * add1[idx + 1]; }
                    if (add2) { v0 += cc2 * add2[idx]; v1 += cc2 * add2[idx + 1]; }
                    C[idx] = v0; C[idx + 1] = v1;
                }
            }
        }
    }
}

// ---------------- embedding gather ----------------
__global__ __launch_bounds__(256)
void embed_kernel(const int* __restrict__ src, const float* __restrict__ W,
                  float* __restrict__ emb)
{
    int t = blockIdx.x, tid = threadIdx.x;
    long row = (long)src[t] * DIM;
#pragma unroll
    for (int k = 0; k < 3; k++)
        emb[(long)t * DIM + tid + k * 256] = W[row + tid + k * 256];
}

// ---------------- attention: scores = scale * Q K^T ----------------
__global__ __launch_bounds__(256)
void attn_scores(const float* __restrict__ qkv, float* __restrict__ scores)
{
    __shared__ __align__(16) float Qs[64][64];
    __shared__ __align__(16) float Ks[64][64];
    int bh = blockIdx.z;
    int b = bh / NH, h = bh % NH;
    int i0 = blockIdx.y * 64;
    int j0 = blockIdx.x * 64;
    int tid = threadIdx.x;
    int tx = tid & 15, ty = tid >> 4;

#pragma unroll
    for (int rep = 0; rep < 4; rep++) {
        int r  = rep * 16 + (tid >> 4);
        int c4 = (tid & 15) * 4;
        float4 q = *(const float4*)&qkv[((long)(b * SEQ + i0 + r)) * (3 * DIM) + h * HD + c4];
        float4 k = *(const float4*)&qkv[((long)(b * SEQ + j0 + r)) * (3 * DIM) + DIM + h * HD + c4];
        Qs[c4+0][r] = q.x; Qs[c4+1][r] = q.y; Qs[c4+2][r] = q.z; Qs[c4+3][r] = q.w;
        Ks[c4+0][r] = k.x; Ks[c4+1][r] = k.y; Ks[c4+2][r] = k.z; Ks[c4+3][r] = k.w;
    }
    __syncthreads();

    float acc[4][4] = {};
#pragma unroll 8
    for (int kk = 0; kk < 64; kk++) {
        float4 qa = *(const float4*)&Qs[kk][ty * 4];
        float4 kb = *(const float4*)&Ks[kk][tx * 4];
        float qr[4] = { qa.x, qa.y, qa.z, qa.w };
        float kr[4] = { kb.x, kb.y, kb.z, kb.w };
#pragma unroll
        for (int i = 0; i < 4; i++)
#pragma unroll
            for (int j = 0; j < 4; j++) acc[i][j] = fmaf(qr[i], kr[j], acc[i][j]);
    }
    const float scale = 0.125f;
    long base = (long)bh * SEQ * SEQ;
#pragma unroll
    for (int i = 0; i < 4; i++)
#pragma unroll
        for (int j = 0; j < 4; j++)
            scores[base + (long)(i0 + ty * 4 + i) * SEQ + j0 + tx * 4 + j] = acc[i][j] * scale;
}

// ---------------- row softmax over 512 ----------------
__global__ __launch_bounds__(256)
void softmax512(float* __restrict__ s)
{
    long base = (long)blockIdx.x * SEQ;
    int tid = threadIdx.x;
    float v0 = s[base + tid], v1 = s[base + 256 + tid];
    __shared__ float red[256];
    red[tid] = fmaxf(v0, v1);
    __syncthreads();
    for (int o = 128; o > 0; o >>= 1) { if (tid < o) red[tid] = fmaxf(red[tid], red[tid + o]); __syncthreads(); }
    float m = red[0];
    __syncthreads();
    float e0 = expf(v0 - m), e1 = expf(v1 - m);
    red[tid] = e0 + e1;
    __syncthreads();
    for (int o = 128; o > 0; o >>= 1) { if (tid < o) red[tid] += red[tid + o]; __syncthreads(); }
    float inv = 1.0f / red[0];
    s[base + tid] = e0 * inv;
    s[base + 256 + tid] = e1 * inv;
}

// ---------------- attention: O = P V ----------------
__global__ __launch_bounds__(256)
void attn_av(const float* __restrict__ qkv, const float* __restrict__ scores,
             float* __restrict__ attn)
{
    __shared__ __align__(16) float Ps[32][64];
    __shared__ __align__(16) float Vs[32][64];
    int bh = blockIdx.z;
    int b = bh / NH, h = bh % NH;
    int i0 = blockIdx.x * 64;
    int tid = threadIdx.x;
    int tx = tid & 15, ty = tid >> 4;
    long sbase = (long)bh * SEQ * SEQ;

    float acc[4][4] = {};
    for (int j0 = 0; j0 < SEQ; j0 += 32) {
        __syncthreads();
#pragma unroll
        for (int rep = 0; rep < 2; rep++) {
            int idx = rep * 256 + tid;
            int r  = idx >> 3;
            int c4 = (idx & 7) * 4;
            float4 p = *(const float4*)&scores[sbase + (long)(i0 + r) * SEQ + j0 + c4];
            Ps[c4+0][r] = p.x; Ps[c4+1][r] = p.y; Ps[c4+2][r] = p.z; Ps[c4+3][r] = p.w;
        }
#pragma unroll
        for (int rep = 0; rep < 2; rep++) {
            int idx = rep * 256 + tid;
            int r  = idx >> 4;
            int c4 = (idx & 15) * 4;
            float4 v = *(const float4*)&qkv[((long)(b * SEQ + j0 + r)) * (3 * DIM) + 2 * DIM + h * HD + c4];
            *(float4*)&Vs[r][c4] = v;
        }
        __syncthreads();
#pragma unroll
        for (int kk = 0; kk < 32; kk++) {
            float4 pa = *(const float4*)&Ps[kk][ty * 4];
            float4 vb = *(const float4*)&Vs[kk][tx * 4];
            float pr[4] = { pa.x, pa.y, pa.z, pa.w };
            float vr[4] = { vb.x, vb.y, vb.z, vb.w };
#pragma unroll
            for (int i = 0; i < 4; i++)
#pragma unroll
                for (int j = 0; j < 4; j++) acc[i][j] = fmaf(pr[i], vr[j], acc[i][j]);
        }
    }
#pragma unroll
    for (int i = 0; i < 4; i++)
#pragma unroll
        for (int j = 0; j < 4; j++)
            attn[((long)(b * SEQ + i0 + ty * 4 + i)) * DIM + h * HD + tx * 4 + j] = acc[i][j];
}

// ---------------- gating ----------------
__global__ __launch_bounds__(256)
void gates_kernel(const float* __restrict__ x, const float* __restrict__ gw,
                  const float* __restrict__ gb, const float* __restrict__ qw,
                  const float* __restrict__ qb, float* __restrict__ gates)
{
    int t = blockIdx.x, tid = threadIdx.x;
    __shared__ float xs[DIM];
    __shared__ float lg[NE], lq[NE];
#pragma unroll
    for (int k = 0; k < 3; k++) xs[tid + k * 256] = x[(long)t * DIM + tid + k * 256];
    __syncthreads();
    int w = tid >> 5, lane = tid & 31;
    float ag = 0.f, aq = 0.f;
    for (int d = lane; d < DIM; d += 32) {
        float xv = xs[d];
        ag = fmaf(xv, gw[w * DIM + d], ag);
        aq = fmaf(xv, qw[w * DIM + d], aq);
    }
    for (int o = 16; o > 0; o >>= 1) {
        ag += __shfl_down_sync(0xffffffffu, ag, o);
        aq += __shfl_down_sync(0xffffffffu, aq, o);
    }
    if (lane == 0) { lg[w] = ag + gb[w]; lq[w] = aq + qb[w]; }
    __syncthreads();
    if (tid == 0) {
        float m = lg[0];
        for (int e = 1; e < NE; e++) m = fmaxf(m, lg[e]);
        float ex[NE], s = 0.f;
        for (int e = 0; e < NE; e++) { ex[e] = expf(lg[e] - m); s += ex[e]; }
        float gg[NE], tot = 0.f;
        for (int e = 0; e < NE; e++) {
            float sm = ex[e] / s;
            float sg = 1.0f / (1.0f + expf(-lq[e]));
            gg[e] = sm * (1.0f + 0.1f * sg);
            tot += gg[e];
        }
        for (int e = 0; e < NE; e++) gates[t * NE + e] = gg[e] / tot;
    }
}

// ---------------- MoE combine + residual + LayerNorm ----------------
__global__ __launch_bounds__(256)
void moe_ln(const float* __restrict__ eo, const float* __restrict__ gates,
            float* __restrict__ x, const float* __restrict__ lng,
            const float* __restrict__ lnb)
{
    int t = blockIdx.x, tid = threadIdx.x;
    __shared__ float gs[NE];
    __shared__ float red[256];
    if (tid < NE) gs[tid] = gates[t * NE + tid];
    __syncthreads();
    float y[3];
    float s = 0.f;
#pragma unroll
    for (int k = 0; k < 3; k++) {
        int d = tid + k * 256;
        float m = 0.f;
#pragma unroll
        for (int e = 0; e < NE; e++)
            m = fmaf(gs[e], eo[((long)e * T_TOK + t) * DIM + d], m);
        float v = x[(long)t * DIM + d] + m;
        y[k] = v; s += v;
    }
    red[tid] = s; __syncthreads();
    for (int o = 128; o > 0; o >>= 1) { if (tid < o) red[tid] += red[tid + o]; __syncthreads(); }
    float mean = red[0] * (1.0f / DIM);
    __syncthreads();
    float s2 = 0.f;
#pragma unroll
    for (int k = 0; k < 3; k++) { float d0 = y[k] - mean; s2 += d0 * d0; }
    red[tid] = s2; __syncthreads();
    for (int o = 128; o > 0; o >>= 1) { if (tid < o) red[tid] += red[tid + o]; __syncthreads(); }
    float inv = rsqrtf(red[0] * (1.0f / DIM) + 1e-5f);
#pragma unroll
    for (int k = 0; k < 3; k++) {
        int d = tid + k * 256;
        x[(long)t * DIM + d] = (y[k] - mean) * inv * lng[d] + lnb[d];
    }
}

// ---------------- host helpers ----------------
static void split_launch(const float* src, unsigned* hi, unsigned* lo, long n)
{
    long n4 = n >> 2;
    int blocks = (int)((n4 + 255) / 256);
    split_permute<<<blocks, 256>>>(src, hi, lo, n4);
}

static void launch_gemm(const unsigned* Ah, const unsigned* Al,
                        const unsigned* Bh, const unsigned* Bl,
                        const float* bias, const float* add1, const float* add2,
                        const float* qs,
                        float* C, unsigned* Chi, unsigned* Clo,
                        int M, int N, int K,
                        long sA, long sB, long sBias, long sC, int batch,
                        float alpha, float beta, float c1, float c2, int gelu)
{
    dim3 grid(N / 128, M / 128, batch);
    gemm_sp<<<grid, 256, 65536>>>(Ah, Al, Bh, Bl, bias, add1, add2, qs,
                                  C, Chi, Clo, M, N, K,
                                  sA, sB, sBias, sC, alpha, beta, c1, c2, gelu);
}

extern "C" void kernel_launch(void* const* d_in, const int* in_sizes, int n_in,
                              void* d_out, int out_size)
{
    const int*   src       = (const int*)  d_in[0];
    const float* qs        = (const float*)d_in[1];
    const float* noise     = (const float*)d_in[2];
    const float* embed_W   = (const float*)d_in[3];
    const float* qproj_w   = (const float*)d_in[4];
    const float* qproj_b   = (const float*)d_in[5];
    const float* pos_w     = (const float*)d_in[6];
    const float* pos_b     = (const float*)d_in[7];
    const float* in_proj_w = (const float*)d_in[8];
    const float* in_proj_b = (const float*)d_in[9];
    const float* out_proj_w= (const float*)d_in[10];
    const float* out_proj_b= (const float*)d_in[11];
    const float* ent_w     = (const float*)d_in[12];
    const float* ent_b     = (const float*)d_in[13];
    const float* gate_w    = (const float*)d_in[14];
    const float* gate_b    = (const float*)d_in[15];
    const float* qgate_w   = (const float*)d_in[16];
    const float* qgate_b   = (const float*)d_in[17];
    const float* e_w1      = (const float*)d_in[18];
    const float* e_b1      = (const float*)d_in[19];
    const float* e_w2      = (const float*)d_in[20];
    const float* e_b2      = (const float*)d_in[21];
    const float* ln_g      = (const float*)d_in[22];
    const float* ln_b      = (const float*)d_in[23];
    const float* fc_w      = (const float*)d_in[24];
    const float* fc_b      = (const float*)d_in[25];
    float* out = (float*)d_out;

    static int attr_done = 0;
    cudaFuncSetAttribute(gemm_sp, cudaFuncAttributeMaxDynamicSharedMemorySize, 65536);
    (void)attr_done;

    float *x, *emb, *tmp, *attn, *qkv, *scores, *eo, *gates;
    cudaGetSymbolAddress((void**)&x,      g_x);
    cudaGetSymbolAddress((void**)&emb,    g_emb);
    cudaGetSymbolAddress((void**)&tmp,    g_tmp);
    cudaGetSymbolAddress((void**)&attn,   g_attn);
    cudaGetSymbolAddress((void**)&qkv,    g_qkv);
    cudaGetSymbolAddress((void**)&scores, g_scores);
    cudaGetSymbolAddress((void**)&eo,     g_eo);
    cudaGetSymbolAddress((void**)&gates,  g_gates);

    unsigned *qpH,*qpL,*poH,*poL,*ipH,*ipL,*opH,*opL,*enH,*enL,*e1H,*e1L,*e2H,*e2L,*fcH,*fcL,*xH,*xL,*hH,*hL;
    cudaGetSymbolAddress((void**)&qpH, w_qproj_h); cudaGetSymbolAddress((void**)&qpL, w_qproj_l);
    cudaGetSymbolAddress((void**)&poH, w_pos_h);   cudaGetSymbolAddress((void**)&poL, w_pos_l);
    cudaGetSymbolAddress((void**)&ipH, w_inp_h);   cudaGetSymbolAddress((void**)&ipL, w_inp_l);
    cudaGetSymbolAddress((void**)&opH, w_outp_h);  cudaGetSymbolAddress((void**)&opL, w_outp_l);
    cudaGetSymbolAddress((void**)&enH, w_ent_h);   cudaGetSymbolAddress((void**)&enL, w_ent_l);
    cudaGetSymbolAddress((void**)&e1H, w_e1_h);    cudaGetSymbolAddress((void**)&e1L, w_e1_l);
    cudaGetSymbolAddress((void**)&e2H, w_e2_h);    cudaGetSymbolAddress((void**)&e2L, w_e2_l);
    cudaGetSymbolAddress((void**)&fcH, w_fc_h);    cudaGetSymbolAddress((void**)&fcL, w_fc_l);
    cudaGetSymbolAddress((void**)&xH,  s_x_h);     cudaGetSymbolAddress((void**)&xL,  s_x_l);
    cudaGetSymbolAddress((void**)&hH,  s_h_h);     cudaGetSymbolAddress((void**)&hL,  s_h_l);

    // --- split all weights (once per launch) ---
    split_launch(qproj_w,   qpH, qpL, (long)DIM * DIM);
    split_launch(pos_w,     poH, poL, (long)DIM * DIM);
    split_launch(in_proj_w, ipH, ipL, (long)NL * 3 * DIM * DIM);
    split_launch(out_proj_w,opH, opL, (long)NL * DIM * DIM);
    split_launch(ent_w,     enH, enL, (long)NL * DIM * DIM);
    split_launch(e_w1,      e1H, e1L, (long)NL * NE * FF * DIM);
    split_launch(e_w2,      e2H, e2L, (long)NL * NE * DIM * FF);
    split_launch(fc_w,      fcH, fcL, (long)VOC * DIM);

    // --- prologue ---
    embed_kernel<<<T_TOK, 256>>>(src, embed_W, emb);
    split_launch(emb, xH, xL, (long)T_TOK * DIM);
    // tmp = emb @ qproj^T + qproj_b
    launch_gemm(xH, xL, qpH, qpL, qproj_b, nullptr, nullptr, nullptr,
                tmp, nullptr, nullptr, T_TOK, DIM, DIM, 0, 0, 0, 0, 1,
                1.f, 1.f, 0.f, 0.f, 0);
    split_launch(noise, xH, xL, (long)T_TOK * DIM);
    // x = 0.01*(noise @ pos^T) + pos_b + (1-qs)*emb + qs*tmp
    launch_gemm(xH, xL, poH, poL, pos_b, emb, tmp, qs,
                x, nullptr, nullptr, T_TOK, DIM, DIM, 0, 0, 0, 0, 1,
                0.01f, 1.f, 0.f, 0.f, 0);

    for (int l = 0; l < NL; l++) {
        // qkv = x @ in_proj^T + b
        split_launch(x, xH, xL, (long)T_TOK * DIM);
        launch_gemm(xH, xL, ipH + (long)l * 884736, ipL + (long)l * 884736,
                    in_proj_b + l * 3 * DIM, nullptr, nullptr, nullptr,
                    qkv, nullptr, nullptr, T_TOK, 3 * DIM, DIM, 0, 0, 0, 0, 1,
                    1.f, 1.f, 0.f, 0.f, 0);
        attn_scores<<<dim3(SEQ / 64, SEQ / 64, BAT * NH), 256>>>(qkv, scores);
        softmax512<<<BAT * NH * SEQ, 256>>>(scores);
        attn_av<<<dim3(SEQ / 64, 1, BAT * NH), 256>>>(qkv, scores, attn);
        // tmp = attn @ out_proj^T + b
        split_launch(attn, xH, xL, (long)T_TOK * DIM);
        launch_gemm(xH, xL, opH + (long)l * 294912, opL + (long)l * 294912,
                    out_proj_b + l * DIM, nullptr, nullptr, nullptr,
                    tmp, nullptr, nullptr, T_TOK, DIM, DIM, 0, 0, 0, 0, 1,
                    1.f, 1.f, 0.f, 0.f, 0);
        // x = x + tmp + 0.1*(tmp @ ent^T + ent_b)
        split_launch(tmp, xH, xL, (long)T_TOK * DIM);
        launch_gemm(xH, xL, enH + (long)l * 294912, enL + (long)l * 294912,
                    ent_b + l * DIM, x, tmp, nullptr,
                    x, nullptr, nullptr, T_TOK, DIM, DIM, 0, 0, 0, 0, 1,
                    0.1f, 0.1f, 1.f, 1.f, 0);
        // gates
        gates_kernel<<<T_TOK, 256>>>(x, gate_w + (long)l * NE * DIM, gate_b + l * NE,
                                     qgate_w + (long)l * NE * DIM, qgate_b + l * NE, gates);
        // h[e] = gelu(x @ e_w1[l,e]^T + e_b1) -> written directly as split bf16
        split_launch(x, xH, xL, (long)T_TOK * DIM);
        launch_gemm(xH, xL, e1H + (long)l * 9437184, e1L + (long)l * 9437184,
                    e_b1 + (long)l * NE * FF, nullptr, nullptr, nullptr,
                    nullptr, hH, hL, T_TOK, FF, DIM,
                    0, (long)FF * DIM, FF, (long)T_TOK * FF, NE,
                    1.f, 1.f, 0.f, 0.f, 1);
        // eo[e] = h[e] @ e_w2[l,e]^T + e_b2
        launch_gemm(hH, hL, e2H + (long)l * 9437184, e2L + (long)l * 9437184,
                    e_b2 + (long)l * NE * DIM, nullptr, nullptr, nullptr,
                    eo, nullptr, nullptr, T_TOK, DIM, FF,
                    (long)T_TOK * FF, (long)DIM * FF, DIM, (long)T_TOK * DIM, NE,
                    1.f, 1.f, 0.f, 0.f, 0);
        // x = LN(x + sum_e gates[t,e]*eo[e,t,:])
        moe_ln<<<T_TOK, 256>>>(eo, gates, x, ln_g + l * DIM, ln_b + l * DIM);
    }

    // logits = x @ fc_w^T + fc_b
    split_launch(x, xH, xL, (long)T_TOK * DIM);
    launch_gemm(xH, xL, fcH, fcL, fc_b, nullptr, nullptr, nullptr,
                out, nullptr, nullptr, T_TOK, VOC, DIM, 0, 0, 0, 0, 1,
                1.f, 1.f, 0.f, 0.f, 0);
}

// round 15
// speedup vs baseline: 1.9682x; 1.0059x over previous
#include <cuda_runtime.h>
#include <cuda_bf16.h>
#include <math.h>

// Problem dims
#define T_TOK 2048   // B*S
#define DIM   768
#define NH    12
#define NL    4
#define NE    8
#define FF    3072
#define VOC   32000
#define SEQ   512
#define BAT   4
#define HD    64

// ---------------- static fp32 scratch ----------------
__device__ float g_x   [T_TOK * DIM];
__device__ float g_emb [T_TOK * DIM];
__device__ float g_tmp [T_TOK * DIM];
__device__ float g_attn[T_TOK * DIM];
__device__ float g_qkv [T_TOK * 3 * DIM];
__device__ float g_scores[(size_t)BAT * NH * SEQ * SEQ];
__device__ float g_eo [(size_t)NE * T_TOK * DIM];
__device__ float g_gates[T_TOK * NE];

// ---------------- split bf16 hi/lo buffers (u32 = packed bf16x2) --------
// layout: [row][chunk(kt)][pos 0..15] with pos = ((p&3)<<2)|(p>>2), p = (k%32)/2
__device__ unsigned w_qproj_h[294912],   w_qproj_l[294912];
__device__ unsigned w_pos_h  [294912],   w_pos_l  [294912];
__device__ unsigned w_inp_h  [3538944],  w_inp_l  [3538944];
__device__ unsigned w_outp_h [1179648],  w_outp_l [1179648];
__device__ unsigned w_ent_h  [1179648],  w_ent_l  [1179648];
__device__ unsigned w_e1_h   [37748736], w_e1_l   [37748736];
__device__ unsigned w_e2_h   [37748736], w_e2_l   [37748736];
__device__ unsigned w_fc_h   [12288000], w_fc_l   [12288000];
__device__ unsigned s_x_h    [786432],   s_x_l    [786432];   // x split
__device__ unsigned s_a_h    [786432],   s_a_l    [786432];   // attn / prologue temp
__device__ unsigned s_t_h    [786432],   s_t_l    [786432];   // tmp split
__device__ unsigned s_h_h    [25165824], s_h_l    [25165824]; // expert hidden

// ---------------- fp32 -> split-permuted bf16 hi/lo converter ----------
__global__ __launch_bounds__(256)
void split_permute(const float* __restrict__ src, unsigned* __restrict__ hi,
                   unsigned* __restrict__ lo, long n4)
{
    long i = (long)blockIdx.x * 256 + threadIdx.x;
    if (i >= n4) return;
    float4 v = ((const float4*)src)[i];
    long k = i * 4;
    long chunk = k >> 5;
    int q = (int)(k & 31);
    int p0 = q >> 1, p1 = p0 + 1;
    int pos0 = ((p0 & 3) << 2) | (p0 >> 2);
    int pos1 = ((p1 & 3) << 2) | (p1 >> 2);

    __nv_bfloat16 hx = __float2bfloat16(v.x), hy = __float2bfloat16(v.y);
    __nv_bfloat16 hz = __float2bfloat16(v.z), hw = __float2bfloat16(v.w);
    __nv_bfloat16 lx = __float2bfloat16(v.x - __bfloat162float(hx));
    __nv_bfloat16 ly = __float2bfloat16(v.y - __bfloat162float(hy));
    __nv_bfloat16 lz = __float2bfloat16(v.z - __bfloat162float(hz));
    __nv_bfloat16 lw = __float2bfloat16(v.w - __bfloat162float(hw));

    hi[chunk * 16 + pos0] = ((unsigned)__bfloat16_as_ushort(hy) << 16) | __bfloat16_as_ushort(hx);
    hi[chunk * 16 + pos1] = ((unsigned)__bfloat16_as_ushort(hw) << 16) | __bfloat16_as_ushort(hz);
    lo[chunk * 16 + pos0] = ((unsigned)__bfloat16_as_ushort(ly) << 16) | __bfloat16_as_ushort(lx);
    lo[chunk * 16 + pos1] = ((unsigned)__bfloat16_as_ushort(lw) << 16) | __bfloat16_as_ushort(lz);
}

// ---------------- mma + cp.async helpers ----------------
__device__ __forceinline__ void mma16816(float* c,
    unsigned a0, unsigned a1, unsigned a2, unsigned a3,
    unsigned b0, unsigned b1)
{
    asm volatile(
        "mma.sync.aligned.m16n8k16.row.col.f32.bf16.bf16.f32 "
        "{%0,%1,%2,%3}, {%4,%5,%6,%7}, {%8,%9}, {%0,%1,%2,%3};"
        : "+f"(c[0]), "+f"(c[1]), "+f"(c[2]), "+f"(c[3])
        : "r"(a0), "r"(a1), "r"(a2), "r"(a3), "r"(b0), "r"(b1));
}
__device__ __forceinline__ void cpa16(unsigned saddr, const void* gaddr) {
    asm volatile("cp.async.ca.shared.global [%0], [%1], 16;" :: "r"(saddr), "l"(gaddr));
}
#define CP_COMMIT() asm volatile("cp.async.commit_group;")
#define CP_WAIT1()  asm volatile("cp.async.wait_group 1;")
#define CP_WAIT0()  asm volatile("cp.async.wait_group 0;")

__device__ __forceinline__ void split_write(unsigned* __restrict__ Chi,
                                            unsigned* __restrict__ Clo,
                                            long rr, long col, int N,
                                            float v0, float v1)
{
    long chunk = rr * (N >> 5) + (col >> 5);
    int p = (int)(col & 31) >> 1;
    int pos = ((p & 3) << 2) | (p >> 2);
    __nv_bfloat16 h0 = __float2bfloat16(v0), h1 = __float2bfloat16(v1);
    __nv_bfloat16 l0 = __float2bfloat16(v0 - __bfloat162float(h0));
    __nv_bfloat16 l1 = __float2bfloat16(v1 - __bfloat162float(h1));
    Chi[chunk * 16 + pos] = ((unsigned)__bfloat16_as_ushort(h1) << 16) | __bfloat16_as_ushort(h0);
    Clo[chunk * 16 + pos] = ((unsigned)__bfloat16_as_ushort(l1) << 16) | __bfloat16_as_ushort(l0);
}

// ---------------- tensor-core GEMM on pre-split operands ----------------
// C[m,n] = f(alpha*sum_k A[m,k]*B[n,k] + beta*bias[n]) + c1*add1 + c2*add2
// qsp: c1=1-*qsp, c2=*qsp. f = exact GELU if do_gelu.
// Writes fp32 C if C!=null; writes split-permuted bf16 hi/lo if Chi!=null (both allowed).
// CTA tile 128 x BN, warp tile 64x64. NTH = 2*(BN/64)*32 threads.
template<int BN, int NTH>
__global__ __launch_bounds__(NTH, 1)
void gemm_sp(const unsigned* __restrict__ Ah_g, const unsigned* __restrict__ Al_g,
             const unsigned* __restrict__ Bh_g, const unsigned* __restrict__ Bl_g,
             const float* __restrict__ bias,
             const float* __restrict__ add1, const float* __restrict__ add2,
             const float* __restrict__ qsp,
             float* __restrict__ C, unsigned* __restrict__ Chi, unsigned* __restrict__ Clo,
             int M, int N, int K,
             long sA, long sB, long sBias, long sC,
             float alpha, float beta, float c1, float c2, int do_gelu)
{
    extern __shared__ unsigned smem_u[];
    constexpr int STAGE_U32 = 4096 + 32 * BN;   // Ah(2048) Al(2048) Bh(BN*16) Bl(BN*16)

    const int bz = blockIdx.z;
    Ah_g += bz * (sA >> 1);  Al_g += bz * (sA >> 1);
    Bh_g += bz * (sB >> 1);  Bl_g += bz * (sB >> 1);
    if (C)    C    += bz * sC;
    if (Chi)  { Chi += bz * (sC >> 1); Clo += bz * (sC >> 1); }
    if (bias) bias += bz * sBias;

    const int n0 = blockIdx.x * BN;
    const int m0 = blockIdx.y * 128;
    const int tid = threadIdx.x;
    const int KC = K >> 5;
    const int nk = KC;

    unsigned sbase = (unsigned)__cvta_generic_to_shared(smem_u);

    constexpr int AI = 512 / NTH;        // A segments (hi or lo) per thread
    constexpr int BI = (BN * 4) / NTH;   // B segments per thread

    auto issue = [&](int kt, int b) {
        unsigned sb = sbase + b * STAGE_U32 * 4;
#pragma unroll
        for (int i = 0; i < AI; i++) {
            int seg = tid + i * NTH;
            int row = seg >> 2, part = seg & 3;
            long g = ((long)(m0 + row) * KC + kt) * 16 + part * 4;
            cpa16(sb + seg * 16, Ah_g + g);
            cpa16(sb + 8192 + seg * 16, Al_g + g);
        }
#pragma unroll
        for (int i = 0; i < BI; i++) {
            int seg = tid + i * NTH;
            int row = seg >> 2, part = seg & 3;
            long g = ((long)(n0 + row) * KC + kt) * 16 + part * 4;
            cpa16(sb + 16384 + seg * 16, Bh_g + g);
            cpa16(sb + 16384 + BN * 64 + seg * 16, Bl_g + g);
        }
    };

    // mma coords: warp grid 2(M) x BN/64(N), warp tile 64x64
    const int lane = tid & 31, wid = tid >> 5;
    const int wm = wid & 1, wn = wid >> 1;
    const int g = lane >> 2, tg = lane & 3;

    float acc[4][8][4];
#pragma unroll
    for (int i = 0; i < 4; i++)
#pragma unroll
        for (int j = 0; j < 8; j++)
#pragma unroll
            for (int r = 0; r < 4; r++) acc[i][j][r] = 0.f;

    auto compute = [&](int b) {
        const unsigned* base = smem_u + b * STAGE_U32;
        const uint4* A4h = (const uint4*)(base);
        const uint4* A4l = (const uint4*)(base + 2048);
        const uint4* B4h = (const uint4*)(base + 4096);
        const uint4* B4l = (const uint4*)(base + 4096 + BN * 16);
        uint4 vbh[8], vbl[8];
#pragma unroll
        for (int nf = 0; nf < 8; nf++) {
            int n = wn * 64 + nf * 8 + g;
            vbh[nf] = B4h[n * 4 + tg];
            vbl[nf] = B4l[n * 4 + tg];
        }
#pragma unroll
        for (int mf = 0; mf < 4; mf++) {
            int r0 = wm * 64 + mf * 16 + g;
            uint4 ah0 = A4h[r0 * 4 + tg];
            uint4 ah8 = A4h[(r0 + 8) * 4 + tg];
            uint4 al0 = A4l[r0 * 4 + tg];
            uint4 al8 = A4l[(r0 + 8) * 4 + tg];
#pragma unroll
            for (int nf = 0; nf < 8; nf++) {
                float* c = acc[mf][nf];
                // k-step 0 (k 0..15): hi*hi + hi*lo + lo*hi
                mma16816(c, ah0.x, ah8.x, ah0.y, ah8.y, vbh[nf].x, vbh[nf].y);
                mma16816(c, ah0.x, ah8.x, ah0.y, ah8.y, vbl[nf].x, vbl[nf].y);
                mma16816(c, al0.x, al8.x, al0.y, al8.y, vbh[nf].x, vbh[nf].y);
                // k-step 1 (k 16..31)
                mma16816(c, ah0.z, ah8.z, ah0.w, ah8.w, vbh[nf].z, vbh[nf].w);
                mma16816(c, ah0.z, ah8.z, ah0.w, ah8.w, vbl[nf].z, vbl[nf].w);
                mma16816(c, al0.z, al8.z, al0.w, al8.w, vbh[nf].z, vbh[nf].w);
            }
        }
    };

    issue(0, 0);
    CP_COMMIT();
    for (int kt = 0; kt < nk; kt++) {
        if (kt + 1 < nk) {
            issue(kt + 1, (kt + 1) & 1);
            CP_COMMIT();
            CP_WAIT1();
        } else {
            CP_WAIT0();
        }
        __syncthreads();
        compute(kt & 1);
        __syncthreads();
    }

    // ---- fused epilogue ----
    float cc1 = c1, cc2 = c2;
    if (qsp) { float q = *qsp; cc1 = 1.0f - q; cc2 = q; }

#pragma unroll
    for (int mf = 0; mf < 4; mf++) {
#pragma unroll
        for (int nf = 0; nf < 8; nf++) {
            int row = m0 + wm * 64 + mf * 16 + g;
            int col = n0 + wn * 64 + nf * 8 + 2 * tg;
            float* c = acc[mf][nf];
#pragma unroll
            for (int half = 0; half < 2; half++) {
                long rr = row + half * 8;
                float v0 = alpha * c[half * 2 + 0];
                float v1 = alpha * c[half * 2 + 1];
                if (bias) { v0 += beta * bias[col]; v1 += beta * bias[col + 1]; }
                if (do_gelu) {
                    v0 = 0.5f * v0 * (1.0f + erff(v0 * 0.7071067811865475f));
                    v1 = 0.5f * v1 * (1.0f + erff(v1 * 0.7071067811865475f));
                }
                long idx = rr * N + col;
                if (add1) { v0 += cc1 * add1[idx]; v1 += cc1 * add1[idx + 1]; }
                if (add2) { v0 += cc2 * add2[idx]; v1 += cc2 * add2[idx + 1]; }
                if (C) { C[idx] = v0; C[idx + 1] = v1; }
                if (Chi) split_write(Chi, Clo, rr, col, N, v0, v1);
            }
        }
    }
}

// ---------------- embedding gather ----------------
__global__ __launch_bounds__(256)
void embed_kernel(const int* __restrict__ src, const float* __restrict__ W,
                  float* __restrict__ emb)
{
    int t = blockIdx.x, tid = threadIdx.x;
    long row = (long)src[t] * DIM;
#pragma unroll
    for (int k = 0; k < 3; k++)
        emb[(long)t * DIM + tid + k * 256] = W[row + tid + k * 256];
}

// ---------------- attention: scores = scale * Q K^T ----------------
__global__ __launch_bounds__(256)
void attn_scores(const float* __restrict__ qkv, float* __restrict__ scores)
{
    __shared__ __align__(16) float Qs[64][64];
    __shared__ __align__(16) float Ks[64][64];
    int bh = blockIdx.z;
    int b = bh / NH, h = bh % NH;
    int i0 = blockIdx.y * 64;
    int j0 = blockIdx.x * 64;
    int tid = threadIdx.x;
    int tx = tid & 15, ty = tid >> 4;

#pragma unroll
    for (int rep = 0; rep < 4; rep++) {
        int r  = rep * 16 + (tid >> 4);
        int c4 = (tid & 15) * 4;
        float4 q = *(const float4*)&qkv[((long)(b * SEQ + i0 + r)) * (3 * DIM) + h * HD + c4];
        float4 k = *(const float4*)&qkv[((long)(b * SEQ + j0 + r)) * (3 * DIM) + DIM + h * HD + c4];
        Qs[c4+0][r] = q.x; Qs[c4+1][r] = q.y; Qs[c4+2][r] = q.z; Qs[c4+3][r] = q.w;
        Ks[c4+0][r] = k.x; Ks[c4+1][r] = k.y; Ks[c4+2][r] = k.z; Ks[c4+3][r] = k.w;
    }
    __syncthreads();

    float acc[4][4] = {};
#pragma unroll 8
    for (int kk = 0; kk < 64; kk++) {
        float4 qa = *(const float4*)&Qs[kk][ty * 4];
        float4 kb = *(const float4*)&Ks[kk][tx * 4];
        float qr[4] = { qa.x, qa.y, qa.z, qa.w };
        float kr[4] = { kb.x, kb.y, kb.z, kb.w };
#pragma unroll
        for (int i = 0; i < 4; i++)
#pragma unroll
            for (int j = 0; j < 4; j++) acc[i][j] = fmaf(qr[i], kr[j], acc[i][j]);
    }
    const float scale = 0.125f;
    long base = (long)bh * SEQ * SEQ;
#pragma unroll
    for (int i = 0; i < 4; i++)
#pragma unroll
        for (int j = 0; j < 4; j++)
            scores[base + (long)(i0 + ty * 4 + i) * SEQ + j0 + tx * 4 + j] = acc[i][j] * scale;
}

// ---------------- row softmax over 512 ----------------
__global__ __launch_bounds__(256)
void softmax512(float* __restrict__ s)
{
    long base = (long)blockIdx.x * SEQ;
    int tid = threadIdx.x;
    float v0 = s[base + tid], v1 = s[base + 256 + tid];
    __shared__ float red[256];
    red[tid] = fmaxf(v0, v1);
    __syncthreads();
    for (int o = 128; o > 0; o >>= 1) { if (tid < o) red[tid] = fmaxf(red[tid], red[tid + o]); __syncthreads(); }
    float m = red[0];
    __syncthreads();
    float e0 = expf(v0 - m), e1 = expf(v1 - m);
    red[tid] = e0 + e1;
    __syncthreads();
    for (int o = 128; o > 0; o >>= 1) { if (tid < o) red[tid] += red[tid + o]; __syncthreads(); }
    float inv = 1.0f / red[0];
    s[base + tid] = e0 * inv;
    s[base + 256 + tid] = e1 * inv;
}

// ---------------- attention: O = P V ----------------
__global__ __launch_bounds__(256)
void attn_av(const float* __restrict__ qkv, const float* __restrict__ scores,
             float* __restrict__ attn)
{
    __shared__ __align__(16) float Ps[32][64];
    __shared__ __align__(16) float Vs[32][64];
    int bh = blockIdx.z;
    int b = bh / NH, h = bh % NH;
    int i0 = blockIdx.x * 64;
    int tid = threadIdx.x;
    int tx = tid & 15, ty = tid >> 4;
    long sbase = (long)bh * SEQ * SEQ;

    float acc[4][4] = {};
    for (int j0 = 0; j0 < SEQ; j0 += 32) {
        __syncthreads();
#pragma unroll
        for (int rep = 0; rep < 2; rep++) {
            int idx = rep * 256 + tid;
            int r  = idx >> 3;
            int c4 = (idx & 7) * 4;
            float4 p = *(const float4*)&scores[sbase + (long)(i0 + r) * SEQ + j0 + c4];
            Ps[c4+0][r] = p.x; Ps[c4+1][r] = p.y; Ps[c4+2][r] = p.z; Ps[c4+3][r] = p.w;
        }
#pragma unroll
        for (int rep = 0; rep < 2; rep++) {
            int idx = rep * 256 + tid;
            int r  = idx >> 4;
            int c4 = (idx & 15) * 4;
            float4 v = *(const float4*)&qkv[((long)(b * SEQ + j0 + r)) * (3 * DIM) + 2 * DIM + h * HD + c4];
            *(float4*)&Vs[r][c4] = v;
        }
        __syncthreads();
#pragma unroll
        for (int kk = 0; kk < 32; kk++) {
            float4 pa = *(const float4*)&Ps[kk][ty * 4];
            float4 vb = *(const float4*)&Vs[kk][tx * 4];
            float pr[4] = { pa.x, pa.y, pa.z, pa.w };
            float vr[4] = { vb.x, vb.y, vb.z, vb.w };
#pragma unroll
            for (int i = 0; i < 4; i++)
#pragma unroll
                for (int j = 0; j < 4; j++) acc[i][j] = fmaf(pr[i], vr[j], acc[i][j]);
        }
    }
#pragma unroll
    for (int i = 0; i < 4; i++)
#pragma unroll
        for (int j = 0; j < 4; j++)
            attn[((long)(b * SEQ + i0 + ty * 4 + i)) * DIM + h * HD + tx * 4 + j] = acc[i][j];
}

// ---------------- gating ----------------
__global__ __launch_bounds__(256)
void gates_kernel(const float* __restrict__ x, const float* __restrict__ gw,
                  const float* __restrict__ gb, const float* __restrict__ qw,
                  const float* __restrict__ qb, float* __restrict__ gates)
{
    int t = blockIdx.x, tid = threadIdx.x;
    __shared__ float xs[DIM];
    __shared__ float lg[NE], lq[NE];
#pragma unroll
    for (int k = 0; k < 3; k++) xs[tid + k * 256] = x[(long)t * DIM + tid + k * 256];
    __syncthreads();
    int w = tid >> 5, lane = tid & 31;
    float ag = 0.f, aq = 0.f;
    for (int d = lane; d < DIM; d += 32) {
        float xv = xs[d];
        ag = fmaf(xv, gw[w * DIM + d], ag);
        aq = fmaf(xv, qw[w * DIM + d], aq);
    }
    for (int o = 16; o > 0; o >>= 1) {
        ag += __shfl_down_sync(0xffffffffu, ag, o);
        aq += __shfl_down_sync(0xffffffffu, aq, o);
    }
    if (lane == 0) { lg[w] = ag + gb[w]; lq[w] = aq + qb[w]; }
    __syncthreads();
    if (tid == 0) {
        float m = lg[0];
        for (int e = 1; e < NE; e++) m = fmaxf(m, lg[e]);
        float ex[NE], s = 0.f;
        for (int e = 0; e < NE; e++) { ex[e] = expf(lg[e] - m); s += ex[e]; }
        float gg[NE], tot = 0.f;
        for (int e = 0; e < NE; e++) {
            float sm = ex[e] / s;
            float sg = 1.0f / (1.0f + expf(-lq[e]));
            gg[e] = sm * (1.0f + 0.1f * sg);
            tot += gg[e];
        }
        for (int e = 0; e < NE; e++) gates[t * NE + e] = gg[e] / tot;
    }
}

// ---------------- MoE combine + residual + LayerNorm + split out --------
__global__ __launch_bounds__(256)
void moe_ln(const float* __restrict__ eo, const float* __restrict__ gates,
            float* __restrict__ x, const float* __restrict__ lng,
            const float* __restrict__ lnb,
            unsigned* __restrict__ xh, unsigned* __restrict__ xl)
{
    int t = blockIdx.x, tid = threadIdx.x;
    __shared__ float gs[NE];
    __shared__ float red[256];
    __shared__ float xn[DIM];
    if (tid < NE) gs[tid] = gates[t * NE + tid];
    __syncthreads();
    float y[3];
    float s = 0.f;
#pragma unroll
    for (int k = 0; k < 3; k++) {
        int d = tid + k * 256;
        float m = 0.f;
#pragma unroll
        for (int e = 0; e < NE; e++)
            m = fmaf(gs[e], eo[((long)e * T_TOK + t) * DIM + d], m);
        float v = x[(long)t * DIM + d] + m;
        y[k] = v; s += v;
    }
    red[tid] = s; __syncthreads();
    for (int o = 128; o > 0; o >>= 1) { if (tid < o) red[tid] += red[tid + o]; __syncthreads(); }
    float mean = red[0] * (1.0f / DIM);
    __syncthreads();
    float s2 = 0.f;
#pragma unroll
    for (int k = 0; k < 3; k++) { float d0 = y[k] - mean; s2 += d0 * d0; }
    red[tid] = s2; __syncthreads();
    for (int o = 128; o > 0; o >>= 1) { if (tid < o) red[tid] += red[tid + o]; __syncthreads(); }
    float inv = rsqrtf(red[0] * (1.0f / DIM) + 1e-5f);
#pragma unroll
    for (int k = 0; k < 3; k++) {
        int d = tid + k * 256;
        float v = (y[k] - mean) * inv * lng[d] + lnb[d];
        x[(long)t * DIM + d] = v;
        xn[d] = v;
    }
    __syncthreads();
    // split-permuted bf16 hi/lo of the new x
    for (int pp = tid; pp < DIM / 2; pp += 256) {
        int d0 = pp * 2;
        float v0 = xn[d0], v1 = xn[d0 + 1];
        long chunk = (long)t * (DIM >> 5) + (d0 >> 5);
        int p = (d0 & 31) >> 1;
        int pos = ((p & 3) << 2) | (p >> 2);
        __nv_bfloat16 h0 = __float2bfloat16(v0), h1 = __float2bfloat16(v1);
        __nv_bfloat16 l0 = __float2bfloat16(v0 - __bfloat162float(h0));
        __nv_bfloat16 l1 = __float2bfloat16(v1 - __bfloat162float(h1));
        xh[chunk * 16 + pos] = ((unsigned)__bfloat16_as_ushort(h1) << 16) | __bfloat16_as_ushort(h0);
        xl[chunk * 16 + pos] = ((unsigned)__bfloat16_as_ushort(l1) << 16) | __bfloat16_as_ushort(l0);
    }
}

// ---------------- host helpers ----------------
static void split_launch(const float* src, unsigned* hi, unsigned* lo, long n)
{
    long n4 = n >> 2;
    int blocks = (int)((n4 + 255) / 256);
    split_permute<<<blocks, 256>>>(src, hi, lo, n4);
}

struct GArgs {
    const unsigned *Ah, *Al, *Bh, *Bl;
    const float *bias, *add1, *add2, *qs;
    float* C; unsigned *Chi, *Clo;
    int M, N, K;
    long sA, sB, sBias, sC; int batch;
    float alpha, beta, c1, c2; int gelu;
};

static void launch256(const GArgs& a)
{
    dim3 grid(a.N / 256, a.M / 128, a.batch);
    gemm_sp<256, 256><<<grid, 256, 98304>>>(a.Ah, a.Al, a.Bh, a.Bl, a.bias, a.add1,
        a.add2, a.qs, a.C, a.Chi, a.Clo, a.M, a.N, a.K, a.sA, a.sB, a.sBias, a.sC,
        a.alpha, a.beta, a.c1, a.c2, a.gelu);
}
static void launch128(const GArgs& a)
{
    dim3 grid(a.N / 128, a.M / 128, a.batch);
    gemm_sp<128, 128><<<grid, 128, 65536>>>(a.Ah, a.Al, a.Bh, a.Bl, a.bias, a.add1,
        a.add2, a.qs, a.C, a.Chi, a.Clo, a.M, a.N, a.K, a.sA, a.sB, a.sBias, a.sC,
        a.alpha, a.beta, a.c1, a.c2, a.gelu);
}

extern "C" void kernel_launch(void* const* d_in, const int* in_sizes, int n_in,
                              void* d_out, int out_size)
{
    const int*   src       = (const int*)  d_in[0];
    const float* qs        = (const float*)d_in[1];
    const float* noise     = (const float*)d_in[2];
    const float* embed_W   = (const float*)d_in[3];
    const float* qproj_w   = (const float*)d_in[4];
    const float* qproj_b   = (const float*)d_in[5];
    const float* pos_w     = (const float*)d_in[6];
    const float* pos_b     = (const float*)d_in[7];
    const float* in_proj_w = (const float*)d_in[8];
    const float* in_proj_b = (const float*)d_in[9];
    const float* out_proj_w= (const float*)d_in[10];
    const float* out_proj_b= (const float*)d_in[11];
    const float* ent_w     = (const float*)d_in[12];
    const float* ent_b     = (const float*)d_in[13];
    const float* gate_w    = (const float*)d_in[14];
    const float* gate_b    = (const float*)d_in[15];
    const float* qgate_w   = (const float*)d_in[16];
    const float* qgate_b   = (const float*)d_in[17];
    const float* e_w1      = (const float*)d_in[18];
    const float* e_b1      = (const float*)d_in[19];
    const float* e_w2      = (const float*)d_in[20];
    const float* e_b2      = (const float*)d_in[21];
    const float* ln_g      = (const float*)d_in[22];
    const float* ln_b      = (const float*)d_in[23];
    const float* fc_w      = (const float*)d_in[24];
    const float* fc_b      = (const float*)d_in[25];
    float* out = (float*)d_out;

    cudaFuncSetAttribute(gemm_sp<256, 256>, cudaFuncAttributeMaxDynamicSharedMemorySize, 98304);
    cudaFuncSetAttribute(gemm_sp<128, 128>, cudaFuncAttributeMaxDynamicSharedMemorySize, 65536);

    float *x, *emb, *tmp, *attn, *qkv, *scores, *eo, *gates;
    cudaGetSymbolAddress((void**)&x,      g_x);
    cudaGetSymbolAddress((void**)&emb,    g_emb);
    cudaGetSymbolAddress((void**)&tmp,    g_tmp);
    cudaGetSymbolAddress((void**)&attn,   g_attn);
    cudaGetSymbolAddress((void**)&qkv,    g_qkv);
    cudaGetSymbolAddress((void**)&scores, g_scores);
    cudaGetSymbolAddress((void**)&eo,     g_eo);
    cudaGetSymbolAddress((void**)&gates,  g_gates);

    unsigned *qpH,*qpL,*poH,*poL,*ipH,*ipL,*opH,*opL,*enH,*enL,*e1H,*e1L,*e2H,*e2L,
             *fcH,*fcL,*sxH,*sxL,*saH,*saL,*stH,*stL,*hH,*hL;
    cudaGetSymbolAddress((void**)&qpH, w_qproj_h); cudaGetSymbolAddress((void**)&qpL, w_qproj_l);
    cudaGetSymbolAddress((void**)&poH, w_pos_h);   cudaGetSymbolAddress((void**)&poL, w_pos_l);
    cudaGetSymbolAddress((void**)&ipH, w_inp_h);   cudaGetSymbolAddress((void**)&ipL, w_inp_l);
    cudaGetSymbolAddress((void**)&opH, w_outp_h);  cudaGetSymbolAddress((void**)&opL, w_outp_l);
    cudaGetSymbolAddress((void**)&enH, w_ent_h);   cudaGetSymbolAddress((void**)&enL, w_ent_l);
    cudaGetSymbolAddress((void**)&e1H, w_e1_h);    cudaGetSymbolAddress((void**)&e1L, w_e1_l);
    cudaGetSymbolAddress((void**)&e2H, w_e2_h);    cudaGetSymbolAddress((void**)&e2L, w_e2_l);
    cudaGetSymbolAddress((void**)&fcH, w_fc_h);    cudaGetSymbolAddress((void**)&fcL, w_fc_l);
    cudaGetSymbolAddress((void**)&sxH, s_x_h);     cudaGetSymbolAddress((void**)&sxL, s_x_l);
    cudaGetSymbolAddress((void**)&saH, s_a_h);     cudaGetSymbolAddress((void**)&saL, s_a_l);
    cudaGetSymbolAddress((void**)&stH, s_t_h);     cudaGetSymbolAddress((void**)&stL, s_t_l);
    cudaGetSymbolAddress((void**)&hH,  s_h_h);     cudaGetSymbolAddress((void**)&hL,  s_h_l);

    // --- split all weights (once per launch) ---
    split_launch(qproj_w,   qpH, qpL, (long)DIM * DIM);
    split_launch(pos_w,     poH, poL, (long)DIM * DIM);
    split_launch(in_proj_w, ipH, ipL, (long)NL * 3 * DIM * DIM);
    split_launch(out_proj_w,opH, opL, (long)NL * DIM * DIM);
    split_launch(ent_w,     enH, enL, (long)NL * DIM * DIM);
    split_launch(e_w1,      e1H, e1L, (long)NL * NE * FF * DIM);
    split_launch(e_w2,      e2H, e2L, (long)NL * NE * DIM * FF);
    split_launch(fc_w,      fcH, fcL, (long)VOC * DIM);

    GArgs a = {};

    // --- prologue ---
    embed_kernel<<<T_TOK, 256>>>(src, embed_W, emb);
    split_launch(emb, saH, saL, (long)T_TOK * DIM);
    // tmp = emb @ qproj^T + qproj_b
    a = { saH, saL, qpH, qpL, qproj_b, nullptr, nullptr, nullptr,
          tmp, nullptr, nullptr, T_TOK, DIM, DIM, 0, 0, 0, 0, 1,
          1.f, 1.f, 0.f, 0.f, 0 };
    launch128(a);
    split_launch(noise, saH, saL, (long)T_TOK * DIM);
    // x = 0.01*(noise @ pos^T) + pos_b + (1-qs)*emb + qs*tmp  (+ split -> sx)
    a = { saH, saL, poH, poL, pos_b, emb, tmp, qs,
          x, sxH, sxL, T_TOK, DIM, DIM, 0, 0, 0, 0, 1,
          0.01f, 1.f, 0.f, 0.f, 0 };
    launch128(a);

    for (int l = 0; l < NL; l++) {
        // qkv = x @ in_proj^T + b
        a = { sxH, sxL, ipH + (long)l * 884736, ipL + (long)l * 884736,
              in_proj_b + l * 3 * DIM, nullptr, nullptr, nullptr,
              qkv, nullptr, nullptr, T_TOK, 3 * DIM, DIM, 0, 0, 0, 0, 1,
              1.f, 1.f, 0.f, 0.f, 0 };
        launch256(a);
        attn_scores<<<dim3(SEQ / 64, SEQ / 64, BAT * NH), 256>>>(qkv, scores);
        softmax512<<<BAT * NH * SEQ, 256>>>(scores);
        attn_av<<<dim3(SEQ / 64, 1, BAT * NH), 256>>>(qkv, scores, attn);
        split_launch(attn, saH, saL, (long)T_TOK * DIM);
        // tmp = attn @ out_proj^T + b  (+ split -> st)
        a = { saH, saL, opH + (long)l * 294912, opL + (long)l * 294912,
              out_proj_b + l * DIM, nullptr, nullptr, nullptr,
              tmp, stH, stL, T_TOK, DIM, DIM, 0, 0, 0, 0, 1,
              1.f, 1.f, 0.f, 0.f, 0 };
        launch128(a);
        // x = x + tmp + 0.1*(tmp @ ent^T + ent_b)  (+ split -> sx)
        a = { stH, stL, enH + (long)l * 294912, enL + (long)l * 294912,
              ent_b + l * DIM, x, tmp, nullptr,
              x, sxH, sxL, T_TOK, DIM, DIM, 0, 0, 0, 0, 1,
              0.1f, 0.1f, 1.f, 1.f, 0 };
        launch128(a);
        // gates
        gates_kernel<<<T_TOK, 256>>>(x, gate_w + (long)l * NE * DIM, gate_b + l * NE,
                                     qgate_w + (long)l * NE * DIM, qgate_b + l * NE, gates);
        // h[e] = gelu(x @ e_w1[l,e]^T + e_b1) -> split only
        a = { sxH, sxL, e1H + (long)l * 9437184, e1L + (long)l * 9437184,
              e_b1 + (long)l * NE * FF, nullptr, nullptr, nullptr,
              nullptr, hH, hL, T_TOK, FF, DIM,
              0, (long)FF * DIM, FF, (long)T_TOK * FF, NE,
              1.f, 1.f, 0.f, 0.f, 1 };
        launch256(a);
        // eo[e] = h[e] @ e_w2[l,e]^T + e_b2
        a = { hH, hL, e2H + (long)l * 9437184, e2L + (long)l * 9437184,
              e_b2 + (long)l * NE * DIM, nullptr, nullptr, nullptr,
              eo, nullptr, nullptr, T_TOK, DIM, FF,
              (long)T_TOK * FF, (long)DIM * FF, DIM, (long)T_TOK * DIM, NE,
              1.f, 1.f, 0.f, 0.f, 0 };
        launch256(a);
        // x = LN(x + sum_e gates[t,e]*eo[e,t,:])  (+ split -> sx)
        moe_ln<<<T_TOK, 256>>>(eo, gates, x, ln_g + l * DIM, ln_b + l * DIM, sxH, sxL);
    }

    // logits = x @ fc_w^T + fc_b
    a = { sxH, sxL, fcH, fcL, fc_b, nullptr, nullptr, nullptr,
          out, nullptr, nullptr, T_TOK, VOC, DIM, 0, 0, 0, 0, 1,
          1.f, 1.f, 0.f, 0.f, 0 };
    launch256(a);
}

// round 16
// speedup vs baseline: 2.2557x; 1.1461x over previous
#include <cuda_runtime.h>
#include <cuda_bf16.h>
#include <math.h>

// Problem dims
#define T_TOK 2048   // B*S
#define DIM   768
#define NH    12
#define NL    4
#define NE    8
#define FF    3072
#define VOC   32000
#define SEQ   512
#define BAT   4
#define HD    64

// ---------------- static fp32 scratch ----------------
__device__ float g_x   [T_TOK * DIM];
__device__ float g_emb [T_TOK * DIM];
__device__ float g_tmp [T_TOK * DIM];
__device__ float g_attn[T_TOK * DIM];
__device__ float g_qkv [T_TOK * 3 * DIM];
__device__ float g_scores[(size_t)BAT * NH * SEQ * SEQ];
__device__ float g_eo [(size_t)NE * T_TOK * DIM];
__device__ float g_gates[T_TOK * NE];

// ---------------- split bf16 hi/lo buffers (u32 = packed bf16x2) --------
// layout: [row][chunk(kt)][pos 0..15] with pos = ((p&3)<<2)|(p>>2), p = (k%32)/2
__device__ unsigned w_qproj_h[294912],   w_qproj_l[294912];
__device__ unsigned w_pos_h  [294912],   w_pos_l  [294912];
__device__ unsigned w_inp_h  [3538944],  w_inp_l  [3538944];
__device__ unsigned w_outp_h [1179648],  w_outp_l [1179648];
__device__ unsigned w_ent_h  [1179648],  w_ent_l  [1179648];
__device__ unsigned w_e1_h   [37748736], w_e1_l   [37748736];
__device__ unsigned w_e2_h   [37748736], w_e2_l   [37748736];
__device__ unsigned w_fc_h   [12288000], w_fc_l   [12288000];
__device__ unsigned s_x_h    [786432],   s_x_l    [786432];   // x split
__device__ unsigned s_a_h    [786432],   s_a_l    [786432];   // attn / prologue temp
__device__ unsigned s_t_h    [786432],   s_t_l    [786432];   // tmp split
__device__ unsigned s_h_h    [25165824], s_h_l    [25165824]; // expert hidden

// ---------------- fp32 -> split-permuted bf16 hi/lo converter ----------
__global__ __launch_bounds__(256)
void split_permute(const float* __restrict__ src, unsigned* __restrict__ hi,
                   unsigned* __restrict__ lo, long n4)
{
    long i = (long)blockIdx.x * 256 + threadIdx.x;
    if (i >= n4) return;
    float4 v = ((const float4*)src)[i];
    long k = i * 4;
    long chunk = k >> 5;
    int q = (int)(k & 31);
    int p0 = q >> 1, p1 = p0 + 1;
    int pos0 = ((p0 & 3) << 2) | (p0 >> 2);
    int pos1 = ((p1 & 3) << 2) | (p1 >> 2);

    __nv_bfloat16 hx = __float2bfloat16(v.x), hy = __float2bfloat16(v.y);
    __nv_bfloat16 hz = __float2bfloat16(v.z), hw = __float2bfloat16(v.w);
    __nv_bfloat16 lx = __float2bfloat16(v.x - __bfloat162float(hx));
    __nv_bfloat16 ly = __float2bfloat16(v.y - __bfloat162float(hy));
    __nv_bfloat16 lz = __float2bfloat16(v.z - __bfloat162float(hz));
    __nv_bfloat16 lw = __float2bfloat16(v.w - __bfloat162float(hw));

    hi[chunk * 16 + pos0] = ((unsigned)__bfloat16_as_ushort(hy) << 16) | __bfloat16_as_ushort(hx);
    hi[chunk * 16 + pos1] = ((unsigned)__bfloat16_as_ushort(hw) << 16) | __bfloat16_as_ushort(hz);
    lo[chunk * 16 + pos0] = ((unsigned)__bfloat16_as_ushort(ly) << 16) | __bfloat16_as_ushort(lx);
    lo[chunk * 16 + pos1] = ((unsigned)__bfloat16_as_ushort(lw) << 16) | __bfloat16_as_ushort(lz);
}

// ---------------- mma + cp.async helpers ----------------
__device__ __forceinline__ void mma16816(float* c,
    unsigned a0, unsigned a1, unsigned a2, unsigned a3,
    unsigned b0, unsigned b1)
{
    asm volatile(
        "mma.sync.aligned.m16n8k16.row.col.f32.bf16.bf16.f32 "
        "{%0,%1,%2,%3}, {%4,%5,%6,%7}, {%8,%9}, {%0,%1,%2,%3};"
        : "+f"(c[0]), "+f"(c[1]), "+f"(c[2]), "+f"(c[3])
        : "r"(a0), "r"(a1), "r"(a2), "r"(a3), "r"(b0), "r"(b1));
}
__device__ __forceinline__ void cpa16(unsigned saddr, const void* gaddr) {
    asm volatile("cp.async.cg.shared.global [%0], [%1], 16;" :: "r"(saddr), "l"(gaddr));
}
#define CP_COMMIT() asm volatile("cp.async.commit_group;")
#define CP_WAIT1()  asm volatile("cp.async.wait_group 1;")
#define CP_WAIT0()  asm volatile("cp.async.wait_group 0;")

__device__ __forceinline__ void split_write(unsigned* __restrict__ Chi,
                                            unsigned* __restrict__ Clo,
                                            long rr, long col, int N,
                                            float v0, float v1)
{
    long chunk = rr * (N >> 5) + (col >> 5);
    int p = (int)(col & 31) >> 1;
    int pos = ((p & 3) << 2) | (p >> 2);
    __nv_bfloat16 h0 = __float2bfloat16(v0), h1 = __float2bfloat16(v1);
    __nv_bfloat16 l0 = __float2bfloat16(v0 - __bfloat162float(h0));
    __nv_bfloat16 l1 = __float2bfloat16(v1 - __bfloat162float(h1));
    Chi[chunk * 16 + pos] = ((unsigned)__bfloat16_as_ushort(h1) << 16) | __bfloat16_as_ushort(h0);
    Clo[chunk * 16 + pos] = ((unsigned)__bfloat16_as_ushort(l1) << 16) | __bfloat16_as_ushort(l0);
}

// ---------------- tensor-core GEMM on pre-split operands ----------------
// C[m,n] = f(alpha*sum_k A[m,k]*B[n,k] + beta*bias[n]) + c1*add1 + c2*add2
// qsp: c1=1-*qsp, c2=*qsp. f = exact GELU if do_gelu.
// Writes fp32 C if C!=null; writes split-permuted bf16 hi/lo if Chi!=null.
// CTA tile 128x128, 8 warps in 2x4 grid, warp tile 64x32. 2 CTAs/SM (TLP).
__global__ __launch_bounds__(256, 2)
void gemm_sp(const unsigned* __restrict__ Ah_g, const unsigned* __restrict__ Al_g,
             const unsigned* __restrict__ Bh_g, const unsigned* __restrict__ Bl_g,
             const float* __restrict__ bias,
             const float* __restrict__ add1, const float* __restrict__ add2,
             const float* __restrict__ qsp,
             float* __restrict__ C, unsigned* __restrict__ Chi, unsigned* __restrict__ Clo,
             int M, int N, int K,
             long sA, long sB, long sBias, long sC,
             float alpha, float beta, float c1, float c2, int do_gelu)
{
    extern __shared__ unsigned smem_u[];   // 2 stages x 8192 u32 = 64KB

    const int bz = blockIdx.z;
    Ah_g += bz * (sA >> 1);  Al_g += bz * (sA >> 1);
    Bh_g += bz * (sB >> 1);  Bl_g += bz * (sB >> 1);
    if (C)    C    += bz * sC;
    if (Chi)  { Chi += bz * (sC >> 1); Clo += bz * (sC >> 1); }
    if (bias) bias += bz * sBias;

    const int n0 = blockIdx.x * 128;
    const int m0 = blockIdx.y * 128;
    const int tid = threadIdx.x;
    const int KC = K >> 5;
    const int nk = KC;

    unsigned sbase = (unsigned)__cvta_generic_to_shared(smem_u);

    // loader: segment s -> row = s>>2, part = s&3 (16B = 4 u32); 512 segs per array
    auto issue = [&](int kt, int b) {
        unsigned sb = sbase + b * 32768;
#pragma unroll
        for (int i = 0; i < 2; i++) {
            int seg = tid + i * 256;
            int row = seg >> 2, part = seg & 3;
            long ga = ((long)(m0 + row) * KC + kt) * 16 + part * 4;
            long gb = ((long)(n0 + row) * KC + kt) * 16 + part * 4;
            cpa16(sb + seg * 16,         Ah_g + ga);
            cpa16(sb +  8192 + seg * 16, Al_g + ga);
            cpa16(sb + 16384 + seg * 16, Bh_g + gb);
            cpa16(sb + 24576 + seg * 16, Bl_g + gb);
        }
    };

    // mma coords: warp grid 2(M) x 4(N), warp tile 64x32
    const int lane = tid & 31, wid = tid >> 5;
    const int wm = wid >> 2, wn = wid & 3;
    const int g = lane >> 2, tg = lane & 3;

    float acc[4][4][4];
#pragma unroll
    for (int i = 0; i < 4; i++)
#pragma unroll
        for (int j = 0; j < 4; j++)
#pragma unroll
            for (int r = 0; r < 4; r++) acc[i][j][r] = 0.f;

    auto compute = [&](int b) {
        const unsigned* base = smem_u + b * 8192;
        const uint4* A4h = (const uint4*)(base);
        const uint4* A4l = (const uint4*)(base + 2048);
        const uint4* B4h = (const uint4*)(base + 4096);
        const uint4* B4l = (const uint4*)(base + 6144);
        uint4 vbh[4], vbl[4];
#pragma unroll
        for (int nf = 0; nf < 4; nf++) {
            int n = wn * 32 + nf * 8 + g;
            vbh[nf] = B4h[n * 4 + tg];
            vbl[nf] = B4l[n * 4 + tg];
        }
#pragma unroll
        for (int mf = 0; mf < 4; mf++) {
            int r0 = wm * 64 + mf * 16 + g;
            uint4 ah0 = A4h[r0 * 4 + tg];
            uint4 ah8 = A4h[(r0 + 8) * 4 + tg];
            uint4 al0 = A4l[r0 * 4 + tg];
            uint4 al8 = A4l[(r0 + 8) * 4 + tg];
#pragma unroll
            for (int nf = 0; nf < 4; nf++) {
                float* c = acc[mf][nf];
                // k-step 0 (k 0..15): hi*hi + hi*lo + lo*hi
                mma16816(c, ah0.x, ah8.x, ah0.y, ah8.y, vbh[nf].x, vbh[nf].y);
                mma16816(c, ah0.x, ah8.x, ah0.y, ah8.y, vbl[nf].x, vbl[nf].y);
                mma16816(c, al0.x, al8.x, al0.y, al8.y, vbh[nf].x, vbh[nf].y);
                // k-step 1 (k 16..31)
                mma16816(c, ah0.z, ah8.z, ah0.w, ah8.w, vbh[nf].z, vbh[nf].w);
                mma16816(c, ah0.z, ah8.z, ah0.w, ah8.w, vbl[nf].z, vbl[nf].w);
                mma16816(c, al0.z, al8.z, al0.w, al8.w, vbh[nf].z, vbh[nf].w);
            }
        }
    };

    issue(0, 0);
    CP_COMMIT();
    for (int kt = 0; kt < nk; kt++) {
        if (kt + 1 < nk) {
            issue(kt + 1, (kt + 1) & 1);
            CP_COMMIT();
            CP_WAIT1();
        } else {
            CP_WAIT0();
        }
        __syncthreads();
        compute(kt & 1);
        __syncthreads();
    }

    // ---- fused epilogue ----
    float cc1 = c1, cc2 = c2;
    if (qsp) { float q = *qsp; cc1 = 1.0f - q; cc2 = q; }

#pragma unroll
    for (int mf = 0; mf < 4; mf++) {
#pragma unroll
        for (int nf = 0; nf < 4; nf++) {
            int row = m0 + wm * 64 + mf * 16 + g;
            int col = n0 + wn * 32 + nf * 8 + 2 * tg;
            float* c = acc[mf][nf];
#pragma unroll
            for (int half = 0; half < 2; half++) {
                long rr = row + half * 8;
                float v0 = alpha * c[half * 2 + 0];
                float v1 = alpha * c[half * 2 + 1];
                if (bias) { v0 += beta * bias[col]; v1 += beta * bias[col + 1]; }
                if (do_gelu) {
                    v0 = 0.5f * v0 * (1.0f + erff(v0 * 0.7071067811865475f));
                    v1 = 0.5f * v1 * (1.0f + erff(v1 * 0.7071067811865475f));
                }
                long idx = rr * N + col;
                if (add1) { v0 += cc1 * add1[idx]; v1 += cc1 * add1[idx + 1]; }
                if (add2) { v0 += cc2 * add2[idx]; v1 += cc2 * add2[idx + 1]; }
                if (C) { C[idx] = v0; C[idx + 1] = v1; }
                if (Chi) split_write(Chi, Clo, rr, col, N, v0, v1);
            }
        }
    }
}

// ---------------- embedding gather ----------------
__global__ __launch_bounds__(256)
void embed_kernel(const int* __restrict__ src, const float* __restrict__ W,
                  float* __restrict__ emb)
{
    int t = blockIdx.x, tid = threadIdx.x;
    long row = (long)src[t] * DIM;
#pragma unroll
    for (int k = 0; k < 3; k++)
        emb[(long)t * DIM + tid + k * 256] = W[row + tid + k * 256];
}

// ---------------- attention: scores = scale * Q K^T ----------------
__global__ __launch_bounds__(256)
void attn_scores(const float* __restrict__ qkv, float* __restrict__ scores)
{
    __shared__ __align__(16) float Qs[64][64];
    __shared__ __align__(16) float Ks[64][64];
    int bh = blockIdx.z;
    int b = bh / NH, h = bh % NH;
    int i0 = blockIdx.y * 64;
    int j0 = blockIdx.x * 64;
    int tid = threadIdx.x;
    int tx = tid & 15, ty = tid >> 4;

#pragma unroll
    for (int rep = 0; rep < 4; rep++) {
        int r  = rep * 16 + (tid >> 4);
        int c4 = (tid & 15) * 4;
        float4 q = *(const float4*)&qkv[((long)(b * SEQ + i0 + r)) * (3 * DIM) + h * HD + c4];
        float4 k = *(const float4*)&qkv[((long)(b * SEQ + j0 + r)) * (3 * DIM) + DIM + h * HD + c4];
        Qs[c4+0][r] = q.x; Qs[c4+1][r] = q.y; Qs[c4+2][r] = q.z; Qs[c4+3][r] = q.w;
        Ks[c4+0][r] = k.x; Ks[c4+1][r] = k.y; Ks[c4+2][r] = k.z; Ks[c4+3][r] = k.w;
    }
    __syncthreads();

    float acc[4][4] = {};
#pragma unroll 8
    for (int kk = 0; kk < 64; kk++) {
        float4 qa = *(const float4*)&Qs[kk][ty * 4];
        float4 kb = *(const float4*)&Ks[kk][tx * 4];
        float qr[4] = { qa.x, qa.y, qa.z, qa.w };
        float kr[4] = { kb.x, kb.y, kb.z, kb.w };
#pragma unroll
        for (int i = 0; i < 4; i++)
#pragma unroll
            for (int j = 0; j < 4; j++) acc[i][j] = fmaf(qr[i], kr[j], acc[i][j]);
    }
    const float scale = 0.125f;
    long base = (long)bh * SEQ * SEQ;
#pragma unroll
    for (int i = 0; i < 4; i++)
#pragma unroll
        for (int j = 0; j < 4; j++)
            scores[base + (long)(i0 + ty * 4 + i) * SEQ + j0 + tx * 4 + j] = acc[i][j] * scale;
}

// ---------------- row softmax over 512 ----------------
__global__ __launch_bounds__(256)
void softmax512(float* __restrict__ s)
{
    long base = (long)blockIdx.x * SEQ;
    int tid = threadIdx.x;
    float v0 = s[base + tid], v1 = s[base + 256 + tid];
    __shared__ float red[256];
    red[tid] = fmaxf(v0, v1);
    __syncthreads();
    for (int o = 128; o > 0; o >>= 1) { if (tid < o) red[tid] = fmaxf(red[tid], red[tid + o]); __syncthreads(); }
    float m = red[0];
    __syncthreads();
    float e0 = expf(v0 - m), e1 = expf(v1 - m);
    red[tid] = e0 + e1;
    __syncthreads();
    for (int o = 128; o > 0; o >>= 1) { if (tid < o) red[tid] += red[tid + o]; __syncthreads(); }
    float inv = 1.0f / red[0];
    s[base + tid] = e0 * inv;
    s[base + 256 + tid] = e1 * inv;
}

// ---------------- attention: O = P V ----------------
__global__ __launch_bounds__(256)
void attn_av(const float* __restrict__ qkv, const float* __restrict__ scores,
             float* __restrict__ attn)
{
    __shared__ __align__(16) float Ps[32][64];
    __shared__ __align__(16) float Vs[32][64];
    int bh = blockIdx.z;
    int b = bh / NH, h = bh % NH;
    int i0 = blockIdx.x * 64;
    int tid = threadIdx.x;
    int tx = tid & 15, ty = tid >> 4;
    long sbase = (long)bh * SEQ * SEQ;

    float acc[4][4] = {};
    for (int j0 = 0; j0 < SEQ; j0 += 32) {
        __syncthreads();
#pragma unroll
        for (int rep = 0; rep < 2; rep++) {
            int idx = rep * 256 + tid;
            int r  = idx >> 3;
            int c4 = (idx & 7) * 4;
            float4 p = *(const float4*)&scores[sbase + (long)(i0 + r) * SEQ + j0 + c4];
            Ps[c4+0][r] = p.x; Ps[c4+1][r] = p.y; Ps[c4+2][r] = p.z; Ps[c4+3][r] = p.w;
        }
#pragma unroll
        for (int rep = 0; rep < 2; rep++) {
            int idx = rep * 256 + tid;
            int r  = idx >> 4;
            int c4 = (idx & 15) * 4;
            float4 v = *(const float4*)&qkv[((long)(b * SEQ + j0 + r)) * (3 * DIM) + 2 * DIM + h * HD + c4];
            *(float4*)&Vs[r][c4] = v;
        }
        __syncthreads();
#pragma unroll
        for (int kk = 0; kk < 32; kk++) {
            float4 pa = *(const float4*)&Ps[kk][ty * 4];
            float4 vb = *(const float4*)&Vs[kk][tx * 4];
            float pr[4] = { pa.x, pa.y, pa.z, pa.w };
            float vr[4] = { vb.x, vb.y, vb.z, vb.w };
#pragma unroll
            for (int i = 0; i < 4; i++)
#pragma unroll
                for (int j = 0; j < 4; j++) acc[i][j] = fmaf(pr[i], vr[j], acc[i][j]);
        }
    }
#pragma unroll
    for (int i = 0; i < 4; i++)
#pragma unroll
        for (int j = 0; j < 4; j++)
            attn[((long)(b * SEQ + i0 + ty * 4 + i)) * DIM + h * HD + tx * 4 + j] = acc[i][j];
}

// ---------------- gating ----------------
__global__ __launch_bounds__(256)
void gates_kernel(const float* __restrict__ x, const float* __restrict__ gw,
                  const float* __restrict__ gb, const float* __restrict__ qw,
                  const float* __restrict__ qb, float* __restrict__ gates)
{
    int t = blockIdx.x, tid = threadIdx.x;
    __shared__ float xs[DIM];
    __shared__ float lg[NE], lq[NE];
#pragma unroll
    for (int k = 0; k < 3; k++) xs[tid + k * 256] = x[(long)t * DIM + tid + k * 256];
    __syncthreads();
    int w = tid >> 5, lane = tid & 31;
    float ag = 0.f, aq = 0.f;
    for (int d = lane; d < DIM; d += 32) {
        float xv = xs[d];
        ag = fmaf(xv, gw[w * DIM + d], ag);
        aq = fmaf(xv, qw[w * DIM + d], aq);
    }
    for (int o = 16; o > 0; o >>= 1) {
        ag += __shfl_down_sync(0xffffffffu, ag, o);
        aq += __shfl_down_sync(0xffffffffu, aq, o);
    }
    if (lane == 0) { lg[w] = ag + gb[w]; lq[w] = aq + qb[w]; }
    __syncthreads();
    if (tid == 0) {
        float m = lg[0];
        for (int e = 1; e < NE; e++) m = fmaxf(m, lg[e]);
        float ex[NE], s = 0.f;
        for (int e = 0; e < NE; e++) { ex[e] = expf(lg[e] - m); s += ex[e]; }
        float gg[NE], tot = 0.f;
        for (int e = 0; e < NE; e++) {
            float sm = ex[e] / s;
            float sg = 1.0f / (1.0f + expf(-lq[e]));
            gg[e] = sm * (1.0f + 0.1f * sg);
            tot += gg[e];
        }
        for (int e = 0; e < NE; e++) gates[t * NE + e] = gg[e] / tot;
    }
}

// ---------------- MoE combine + residual + LayerNorm + split out --------
__global__ __launch_bounds__(256)
void moe_ln(const float* __restrict__ eo, const float* __restrict__ gates,
            float* __restrict__ x, const float* __restrict__ lng,
            const float* __restrict__ lnb,
            unsigned* __restrict__ xh, unsigned* __restrict__ xl)
{
    int t = blockIdx.x, tid = threadIdx.x;
    __shared__ float gs[NE];
    __shared__ float red[256];
    __shared__ float xn[DIM];
    if (tid < NE) gs[tid] = gates[t * NE + tid];
    __syncthreads();
    float y[3];
    float s = 0.f;
#pragma unroll
    for (int k = 0; k < 3; k++) {
        int d = tid + k * 256;
        float m = 0.f;
#pragma unroll
        for (int e = 0; e < NE; e++)
            m = fmaf(gs[e], eo[((long)e * T_TOK + t) * DIM + d], m);
        float v = x[(long)t * DIM + d] + m;
        y[k] = v; s += v;
    }
    red[tid] = s; __syncthreads();
    for (int o = 128; o > 0; o >>= 1) { if (tid < o) red[tid] += red[tid + o]; __syncthreads(); }
    float mean = red[0] * (1.0f / DIM);
    __syncthreads();
    float s2 = 0.f;
#pragma unroll
    for (int k = 0; k < 3; k++) { float d0 = y[k] - mean; s2 += d0 * d0; }
    red[tid] = s2; __syncthreads();
    for (int o = 128; o > 0; o >>= 1) { if (tid < o) red[tid] += red[tid + o]; __syncthreads(); }
    float inv = rsqrtf(red[0] * (1.0f / DIM) + 1e-5f);
#pragma unroll
    for (int k = 0; k < 3; k++) {
        int d = tid + k * 256;
        float v = (y[k] - mean) * inv * lng[d] + lnb[d];
        x[(long)t * DIM + d] = v;
        xn[d] = v;
    }
    __syncthreads();
    // split-permuted bf16 hi/lo of the new x
    for (int pp = tid; pp < DIM / 2; pp += 256) {
        int d0 = pp * 2;
        float v0 = xn[d0], v1 = xn[d0 + 1];
        long chunk = (long)t * (DIM >> 5) + (d0 >> 5);
        int p = (d0 & 31) >> 1;
        int pos = ((p & 3) << 2) | (p >> 2);
        __nv_bfloat16 h0 = __float2bfloat16(v0), h1 = __float2bfloat16(v1);
        __nv_bfloat16 l0 = __float2bfloat16(v0 - __bfloat162float(h0));
        __nv_bfloat16 l1 = __float2bfloat16(v1 - __bfloat162float(h1));
        xh[chunk * 16 + pos] = ((unsigned)__bfloat16_as_ushort(h1) << 16) | __bfloat16_as_ushort(h0);
        xl[chunk * 16 + pos] = ((unsigned)__bfloat16_as_ushort(l1) << 16) | __bfloat16_as_ushort(l0);
    }
}

// ---------------- host helpers ----------------
static void split_launch(const float* src, unsigned* hi, unsigned* lo, long n)
{
    long n4 = n >> 2;
    int blocks = (int)((n4 + 255) / 256);
    split_permute<<<blocks, 256>>>(src, hi, lo, n4);
}

struct GArgs {
    const unsigned *Ah, *Al, *Bh, *Bl;
    const float *bias, *add1, *add2, *qs;
    float* C; unsigned *Chi, *Clo;
    int M, N, K;
    long sA, sB, sBias, sC; int batch;
    float alpha, beta, c1, c2; int gelu;
};

static void launch_gemm(const GArgs& a)
{
    dim3 grid(a.N / 128, a.M / 128, a.batch);
    gemm_sp<<<grid, 256, 65536>>>(a.Ah, a.Al, a.Bh, a.Bl, a.bias, a.add1,
        a.add2, a.qs, a.C, a.Chi, a.Clo, a.M, a.N, a.K, a.sA, a.sB, a.sBias, a.sC,
        a.alpha, a.beta, a.c1, a.c2, a.gelu);
}

extern "C" void kernel_launch(void* const* d_in, const int* in_sizes, int n_in,
                              void* d_out, int out_size)
{
    const int*   src       = (const int*)  d_in[0];
    const float* qs        = (const float*)d_in[1];
    const float* noise     = (const float*)d_in[2];
    const float* embed_W   = (const float*)d_in[3];
    const float* qproj_w   = (const float*)d_in[4];
    const float* qproj_b   = (const float*)d_in[5];
    const float* pos_w     = (const float*)d_in[6];
    const float* pos_b     = (const float*)d_in[7];
    const float* in_proj_w = (const float*)d_in[8];
    const float* in_proj_b = (const float*)d_in[9];
    const float* out_proj_w= (const float*)d_in[10];
    const float* out_proj_b= (const float*)d_in[11];
    const float* ent_w     = (const float*)d_in[12];
    const float* ent_b     = (const float*)d_in[13];
    const float* gate_w    = (const float*)d_in[14];
    const float* gate_b    = (const float*)d_in[15];
    const float* qgate_w   = (const float*)d_in[16];
    const float* qgate_b   = (const float*)d_in[17];
    const float* e_w1      = (const float*)d_in[18];
    const float* e_b1      = (const float*)d_in[19];
    const float* e_w2      = (const float*)d_in[20];
    const float* e_b2      = (const float*)d_in[21];
    const float* ln_g      = (const float*)d_in[22];
    const float* ln_b      = (const float*)d_in[23];
    const float* fc_w      = (const float*)d_in[24];
    const float* fc_b      = (const float*)d_in[25];
    float* out = (float*)d_out;

    cudaFuncSetAttribute(gemm_sp, cudaFuncAttributeMaxDynamicSharedMemorySize, 65536);

    float *x, *emb, *tmp, *attn, *qkv, *scores, *eo, *gates;
    cudaGetSymbolAddress((void**)&x,      g_x);
    cudaGetSymbolAddress((void**)&emb,    g_emb);
    cudaGetSymbolAddress((void**)&tmp,    g_tmp);
    cudaGetSymbolAddress((void**)&attn,   g_attn);
    cudaGetSymbolAddress((void**)&qkv,    g_qkv);
    cudaGetSymbolAddress((void**)&scores, g_scores);
    cudaGetSymbolAddress((void**)&eo,     g_eo);
    cudaGetSymbolAddress((void**)&gates,  g_gates);

    unsigned *qpH,*qpL,*poH,*poL,*ipH,*ipL,*opH,*opL,*enH,*enL,*e1H,*e1L,*e2H,*e2L,
             *fcH,*fcL,*sxH,*sxL,*saH,*saL,*stH,*stL,*hH,*hL;
    cudaGetSymbolAddress((void**)&qpH, w_qproj_h); cudaGetSymbolAddress((void**)&qpL, w_qproj_l);
    cudaGetSymbolAddress((void**)&poH, w_pos_h);   cudaGetSymbolAddress((void**)&poL, w_pos_l);
    cudaGetSymbolAddress((void**)&ipH, w_inp_h);   cudaGetSymbolAddress((void**)&ipL, w_inp_l);
    cudaGetSymbolAddress((void**)&opH, w_outp_h);  cudaGetSymbolAddress((void**)&opL, w_outp_l);
    cudaGetSymbolAddress((void**)&enH, w_ent_h);   cudaGetSymbolAddress((void**)&enL, w_ent_l);
    cudaGetSymbolAddress((void**)&e1H, w_e1_h);    cudaGetSymbolAddress((void**)&e1L, w_e1_l);
    cudaGetSymbolAddress((void**)&e2H, w_e2_h);    cudaGetSymbolAddress((void**)&e2L, w_e2_l);
    cudaGetSymbolAddress((void**)&fcH, w_fc_h);    cudaGetSymbolAddress((void**)&fcL, w_fc_l);
    cudaGetSymbolAddress((void**)&sxH, s_x_h);     cudaGetSymbolAddress((void**)&sxL, s_x_l);
    cudaGetSymbolAddress((void**)&saH, s_a_h);     cudaGetSymbolAddress((void**)&saL, s_a_l);
    cudaGetSymbolAddress((void**)&stH, s_t_h);     cudaGetSymbolAddress((void**)&stL, s_t_l);
    cudaGetSymbolAddress((void**)&hH,  s_h_h);     cudaGetSymbolAddress((void**)&hL,  s_h_l);

    // --- split all weights (once per launch) ---
    split_launch(qproj_w,   qpH, qpL, (long)DIM * DIM);
    split_launch(pos_w,     poH, poL, (long)DIM * DIM);
    split_launch(in_proj_w, ipH, ipL, (long)NL * 3 * DIM * DIM);
    split_launch(out_proj_w,opH, opL, (long)NL * DIM * DIM);
    split_launch(ent_w,     enH, enL, (long)NL * DIM * DIM);
    split_launch(e_w1,      e1H, e1L, (long)NL * NE * FF * DIM);
    split_launch(e_w2,      e2H, e2L, (long)NL * NE * DIM * FF);
    split_launch(fc_w,      fcH, fcL, (long)VOC * DIM);

    GArgs a = {};

    // --- prologue ---
    embed_kernel<<<T_TOK, 256>>>(src, embed_W, emb);
    split_launch(emb, saH, saL, (long)T_TOK * DIM);
    // tmp = emb @ qproj^T + qproj_b
    a = { saH, saL, qpH, qpL, qproj_b, nullptr, nullptr, nullptr,
          tmp, nullptr, nullptr, T_TOK, DIM, DIM, 0, 0, 0, 0, 1,
          1.f, 1.f, 0.f, 0.f, 0 };
    launch_gemm(a);
    split_launch(noise, saH, saL, (long)T_TOK * DIM);
    // x = 0.01*(noise @ pos^T) + pos_b + (1-qs)*emb + qs*tmp  (+ split -> sx)
    a = { saH, saL, poH, poL, pos_b, emb, tmp, qs,
          x, sxH, sxL, T_TOK, DIM, DIM, 0, 0, 0, 0, 1,
          0.01f, 1.f, 0.f, 0.f, 0 };
    launch_gemm(a);

    for (int l = 0; l < NL; l++) {
        // qkv = x @ in_proj^T + b
        a = { sxH, sxL, ipH + (long)l * 884736, ipL + (long)l * 884736,
              in_proj_b + l * 3 * DIM, nullptr, nullptr, nullptr,
              qkv, nullptr, nullptr, T_TOK, 3 * DIM, DIM, 0, 0, 0, 0, 1,
              1.f, 1.f, 0.f, 0.f, 0 };
        launch_gemm(a);
        attn_scores<<<dim3(SEQ / 64, SEQ / 64, BAT * NH), 256>>>(qkv, scores);
        softmax512<<<BAT * NH * SEQ, 256>>>(scores);
        attn_av<<<dim3(SEQ / 64, 1, BAT * NH), 256>>>(qkv, scores, attn);
        split_launch(attn, saH, saL, (long)T_TOK * DIM);
        // tmp = attn @ out_proj^T + b  (+ split -> st)
        a = { saH, saL, opH + (long)l * 294912, opL + (long)l * 294912,
              out_proj_b + l * DIM, nullptr, nullptr, nullptr,
              tmp, stH, stL, T_TOK, DIM, DIM, 0, 0, 0, 0, 1,
              1.f, 1.f, 0.f, 0.f, 0 };
        launch_gemm(a);
        // x = x + tmp + 0.1*(tmp @ ent^T + ent_b)  (+ split -> sx)
        a = { stH, stL, enH + (long)l * 294912, enL + (long)l * 294912,
              ent_b + l * DIM, x, tmp, nullptr,
              x, sxH, sxL, T_TOK, DIM, DIM, 0, 0, 0, 0, 1,
              0.1f, 0.1f, 1.f, 1.f, 0 };
        launch_gemm(a);
        // gates
        gates_kernel<<<T_TOK, 256>>>(x, gate_w + (long)l * NE * DIM, gate_b + l * NE,
                                     qgate_w + (long)l * NE * DIM, qgate_b + l * NE, gates);
        // h[e] = gelu(x @ e_w1[l,e]^T + e_b1) -> split only
        a = { sxH, sxL, e1H + (long)l * 9437184, e1L + (long)l * 9437184,
              e_b1 + (long)l * NE * FF, nullptr, nullptr, nullptr,
              nullptr, hH, hL, T_TOK, FF, DIM,
              0, (long)FF * DIM, FF, (long)T_TOK * FF, NE,
              1.f, 1.f, 0.f, 0.f, 1 };
        launch_gemm(a);
        // eo[e] = h[e] @ e_w2[l,e]^T + e_b2
        a = { hH, hL, e2H + (long)l * 9437184, e2L + (long)l * 9437184,
              e_b2 + (long)l * NE * DIM, nullptr, nullptr, nullptr,
              eo, nullptr, nullptr, T_TOK, DIM, FF,
              (long)T_TOK * FF, (long)DIM * FF, DIM, (long)T_TOK * DIM, NE,
              1.f, 1.f, 0.f, 0.f, 0 };
        launch_gemm(a);
        // x = LN(x + sum_e gates[t,e]*eo[e,t,:])  (+ split -> sx)
        moe_ln<<<T_TOK, 256>>>(eo, gates, x, ln_g + l * DIM, ln_b + l * DIM, sxH, sxL);
    }

    // logits = x @ fc_w^T + fc_b
    a = { sxH, sxL, fcH, fcL, fc_b, nullptr, nullptr, nullptr,
          out, nullptr, nullptr, T_TOK, VOC, DIM, 0, 0, 0, 0, 1,
          1.f, 1.f, 0.f, 0.f, 0 };
    launch_gemm(a);
}